// round 7
// baseline (speedup 1.0000x reference)
#include <cuda_runtime.h>

// Problem constants
#define BB 2
#define TT 512
#define UU 48
#define DD 512
#define HH 1024
#define KK 128
#define SEG_ELEMS (BB*KK*TT)   // 131072 floats, first part of d_out
// joint part: BB*UU*TT*KK = 6291456 floats after SEG_ELEMS

// Scratch (allocation-free rule: __device__ globals)
__device__ float g_img_pre[BB*TT*HH];   // [(b*T+t)][h]  : img_feature @ Wi^T
__device__ float g_lab_pre[BB*UU*HH];   // [(b*U+u)][h]  : label_feature @ Wl^T + b1
__device__ float g_w2t[HH*KK];          // [h][k]        : W2 transposed

typedef unsigned long long u64;

__device__ __forceinline__ u64 pack2(float lo, float hi){
    u64 r; asm("mov.b64 %0, {%1, %2};" : "=l"(r) : "f"(lo), "f"(hi)); return r;
}
__device__ __forceinline__ void unpack2(u64 v, float& lo, float& hi){
    asm("mov.b64 {%0, %1}, %2;" : "=f"(lo), "=f"(hi) : "l"(v));
}
// Packed fp32x2 FMA: the only route to 128 FP32 FMA lanes/cyc/SM on sm_103a.
__device__ __forceinline__ void ffma2(u64& c, u64 a, u64 b){
    asm("fma.rn.f32x2 %0, %1, %2, %0;" : "+l"(c) : "l"(a), "l"(b));
}

__device__ __forceinline__ float tanh_fast(float x){
    x = fminf(10.f, fmaxf(-10.f, x));
    float e = __expf(2.f*x);
    return 1.f - __fdividef(2.f, e + 1.f);
}

// ---------------------------------------------------------------------------
// W2 (K=128, H=1024) -> W2T (H, K), classic smem-tile transpose
// ---------------------------------------------------------------------------
__global__ void transpose_w2_kernel(const float* __restrict__ W2){
    __shared__ float tile[32][33];
    int h = blockIdx.x*32 + threadIdx.x;
    int k0 = blockIdx.y*32;
    #pragma unroll
    for (int j = 0; j < 32; j += 8)
        tile[threadIdx.y + j][threadIdx.x] = W2[(k0 + threadIdx.y + j)*HH + h];
    __syncthreads();
    int k  = k0 + threadIdx.x;
    int h0 = blockIdx.x*32;
    #pragma unroll
    for (int j = 0; j < 32; j += 8)
        g_w2t[(h0 + threadIdx.y + j)*KK + k] = tile[threadIdx.x][threadIdx.y + j];
}

// ---------------------------------------------------------------------------
// Prep kernel: 3 NT-GEMMs in one grid (80 CTAs, one wave)
//   job0 (blocks 0..63):  img_pre[bt][h]  = img_feature @ Wi^T          (1024x1024xK512)
//   job1 (blocks 64..71): lab_pre[bu][h]  = label_feature @ Wl^T + b1   (96x1024xK512)
//   job2 (blocks 72..79): img_seg_score   = (img_feature @ conv_w^T + conv_b)*mask
//                         written to d_out[(b*K+k)*T + t]               (1024x128xK512)
// 128x128 C-tile, 256 threads, 8x8 micro-tile with packed FFMA2.
// ---------------------------------------------------------------------------
__global__ __launch_bounds__(256, 2) void prep_kernel(
    const float* __restrict__ img, const float* __restrict__ lab,
    const float* __restrict__ W1, const float* __restrict__ b1,
    const float* __restrict__ convw, const float* __restrict__ convb,
    const float* __restrict__ masks, float* __restrict__ out)
{
    __shared__ float As[128][16];   // [m][d] m-major (vectorized stores, broadcast reads)
    __shared__ float Bs[16][132];   // [d][n] padded: 132*4=528B rows, 8B-divisible

    int bx = blockIdx.x;
    const float* A; const float* Bp;
    int ldb, M, m0, n0, job;
    if (bx < 64)      { job=0; A=img; Bp=W1+DD; ldb=2*DD; M=BB*TT; m0=(bx&7)*128;  n0=(bx>>3)*128; }
    else if (bx < 72) { job=1; A=lab; Bp=W1;    ldb=2*DD; M=BB*UU; m0=0;           n0=(bx-64)*128; }
    else              { job=2; A=img; Bp=convw; ldb=DD;   M=BB*TT; m0=(bx-72)*128; n0=0; }

    int tid = threadIdx.x;
    int tx = tid & 15, ty = tid >> 4;
    int lm = tid >> 2, lq = (tid & 3) * 4;

    u64 c2[8][4];
    #pragma unroll
    for (int i = 0; i < 8; i++)
        #pragma unroll
        for (int j = 0; j < 4; j++) c2[i][j] = 0ull;

    for (int d0 = 0; d0 < DD; d0 += 16){
        int m1 = m0 + lm, m2 = m0 + lm + 64;
        float4 va1 = (m1 < M) ? *(const float4*)&A[m1*DD + d0 + lq] : make_float4(0,0,0,0);
        float4 va2 = (m2 < M) ? *(const float4*)&A[m2*DD + d0 + lq] : make_float4(0,0,0,0);
        float4 vb1 = *(const float4*)&Bp[(n0+lm)*ldb + d0 + lq];
        float4 vb2 = *(const float4*)&Bp[(n0+lm+64)*ldb + d0 + lq];
        *(float4*)&As[lm][lq]    = va1;
        *(float4*)&As[lm+64][lq] = va2;
        Bs[lq+0][lm] = vb1.x; Bs[lq+1][lm] = vb1.y; Bs[lq+2][lm] = vb1.z; Bs[lq+3][lm] = vb1.w;
        Bs[lq+0][lm+64] = vb2.x; Bs[lq+1][lm+64] = vb2.y; Bs[lq+2][lm+64] = vb2.z; Bs[lq+3][lm+64] = vb2.w;
        __syncthreads();
        #pragma unroll
        for (int dd = 0; dd < 16; dd++){
            u64 a2[8], bv[4];
            #pragma unroll
            for (int j = 0; j < 4; j++) bv[j] = *(const u64*)&Bs[dd][32*j + 2*tx];
            #pragma unroll
            for (int i = 0; i < 8; i++){ float av = As[ty + 16*i][dd]; a2[i] = pack2(av, av); }
            #pragma unroll
            for (int i = 0; i < 8; i++)
                #pragma unroll
                for (int j = 0; j < 4; j++) ffma2(c2[i][j], a2[i], bv[j]);
        }
        __syncthreads();
    }

    if (job == 0){
        #pragma unroll
        for (int i = 0; i < 8; i++){
            int m = m0 + ty + 16*i;
            #pragma unroll
            for (int j = 0; j < 4; j++){
                float lo, hi; unpack2(c2[i][j], lo, hi);
                *(float2*)&g_img_pre[m*HH + n0 + 32*j + 2*tx] = make_float2(lo, hi);
            }
        }
    } else if (job == 1){
        #pragma unroll
        for (int i = 0; i < 8; i++){
            int m = ty + 16*i;
            if (m < BB*UU){
                #pragma unroll
                for (int j = 0; j < 4; j++){
                    int n = n0 + 32*j + 2*tx;
                    float2 bb = *(const float2*)&b1[n];
                    float lo, hi; unpack2(c2[i][j], lo, hi);
                    *(float2*)&g_lab_pre[m*HH + n] = make_float2(lo + bb.x, hi + bb.y);
                }
            }
        }
    } else {
        #pragma unroll
        for (int i = 0; i < 8; i++){
            int m = m0 + ty + 16*i;
            float mk = masks[m];
            int b = m >> 9, t = m & 511;
            #pragma unroll
            for (int j = 0; j < 4; j++){
                int n = 32*j + 2*tx;
                float2 cb = *(const float2*)&convb[n];
                float lo, hi; unpack2(c2[i][j], lo, hi);
                out[(b*KK + n  )*TT + t] = (lo + cb.x)*mk;
                out[(b*KK + n+1)*TT + t] = (hi + cb.y)*mk;
            }
        }
    }
}

// ---------------------------------------------------------------------------
// Main fused kernel: joint_score[(b,u),t,k] = log_softmax_k( tanh(img_pre+lab_pre) @ W2T + b2 )
// Grid: 96 (b,u)-pairs x 4 t-tiles = 384 CTAs. 128(t) x 128(k) C-tile,
// reduction over H=1024 in 16-chunks; tanh applied while staging A into smem.
// ---------------------------------------------------------------------------
__global__ __launch_bounds__(256, 2) void joint_kernel(const float* __restrict__ b2,
                                                       float* __restrict__ out)
{
    __shared__ float As[128][16];   // tanh-activated A tile, [t][h]
    __shared__ float Bs[16][128];   // W2T chunk, [h][k]

    int pair = blockIdx.x >> 2;            // 0..95 = b*U+u
    int t0   = (blockIdx.x & 3) * 128;
    int b    = pair / UU;

    int tid = threadIdx.x;
    int tx = tid & 15, ty = tid >> 4;
    int lm = tid >> 2, lq = (tid & 3) * 4;

    const float* imgp = g_img_pre + (b*TT + t0)*HH;
    const float* labp = g_lab_pre + pair*HH;

    u64 c2[8][4];
    #pragma unroll
    for (int i = 0; i < 8; i++)
        #pragma unroll
        for (int j = 0; j < 4; j++) c2[i][j] = 0ull;

    int bhh = tid >> 4;            // 0..15
    int bk  = (tid & 15) * 8;      // 0..120

    for (int h0 = 0; h0 < HH; h0 += 16){
        // B chunk: fully coalesced from pre-transposed W2T
        *(float4*)&Bs[bhh][bk]   = *(const float4*)&g_w2t[(h0+bhh)*KK + bk];
        *(float4*)&Bs[bhh][bk+4] = *(const float4*)&g_w2t[(h0+bhh)*KK + bk + 4];
        // A chunk: tanh(img_pre + lab_pre) generated on the fly
        float4 lv = *(const float4*)&labp[h0 + lq];
        float4 i1 = *(const float4*)&imgp[lm*HH + h0 + lq];
        float4 i2 = *(const float4*)&imgp[(lm+64)*HH + h0 + lq];
        float4 r1, r2;
        r1.x = tanh_fast(i1.x + lv.x); r1.y = tanh_fast(i1.y + lv.y);
        r1.z = tanh_fast(i1.z + lv.z); r1.w = tanh_fast(i1.w + lv.w);
        r2.x = tanh_fast(i2.x + lv.x); r2.y = tanh_fast(i2.y + lv.y);
        r2.z = tanh_fast(i2.z + lv.z); r2.w = tanh_fast(i2.w + lv.w);
        *(float4*)&As[lm][lq]    = r1;
        *(float4*)&As[lm+64][lq] = r2;
        __syncthreads();
        #pragma unroll
        for (int dd = 0; dd < 16; dd++){
            u64 a2[8], bv[4];
            #pragma unroll
            for (int j = 0; j < 4; j++) bv[j] = *(const u64*)&Bs[dd][32*j + 2*tx];
            #pragma unroll
            for (int i = 0; i < 8; i++){ float av = As[ty + 16*i][dd]; a2[i] = pack2(av, av); }
            #pragma unroll
            for (int i = 0; i < 8; i++)
                #pragma unroll
                for (int j = 0; j < 4; j++) ffma2(c2[i][j], a2[i], bv[j]);
        }
        __syncthreads();
    }

    // Fused epilogue: +b2, log_softmax over k (row spread across 16 lanes of a half-warp)
    float* outj = out + SEG_ELEMS + (pair*TT + t0)*KK;
    float bb2[8];
    #pragma unroll
    for (int j = 0; j < 4; j++){
        float2 v = *(const float2*)&b2[32*j + 2*tx];
        bb2[2*j] = v.x; bb2[2*j+1] = v.y;
    }
    #pragma unroll
    for (int i = 0; i < 8; i++){
        float v[8];
        #pragma unroll
        for (int j = 0; j < 4; j++) unpack2(c2[i][j], v[2*j], v[2*j+1]);
        #pragma unroll
        for (int j = 0; j < 8; j++) v[j] += bb2[j];
        float mx = v[0];
        #pragma unroll
        for (int j = 1; j < 8; j++) mx = fmaxf(mx, v[j]);
        #pragma unroll
        for (int d = 1; d < 16; d <<= 1) mx = fmaxf(mx, __shfl_xor_sync(0xffffffffu, mx, d));
        float s = 0.f;
        #pragma unroll
        for (int j = 0; j < 8; j++) s += __expf(v[j] - mx);
        #pragma unroll
        for (int d = 1; d < 16; d <<= 1) s += __shfl_xor_sync(0xffffffffu, s, d);
        float L = mx + __logf(s);
        float* row = outj + (ty + 16*i)*KK;
        #pragma unroll
        for (int j = 0; j < 4; j++)
            *(float2*)&row[32*j + 2*tx] = make_float2(v[2*j] - L, v[2*j+1] - L);
    }
}

// ---------------------------------------------------------------------------
extern "C" void kernel_launch(void* const* d_in, const int* in_sizes, int n_in,
                              void* d_out, int out_size)
{
    (void)in_sizes; (void)n_in; (void)out_size;
    const float* img   = (const float*)d_in[0];  // (B,T,D)
    const float* lab   = (const float*)d_in[1];  // (B,U,D)
    const float* masks = (const float*)d_in[2];  // (B,1,T)
    const float* W1    = (const float*)d_in[3];  // (H,2D)
    const float* b1    = (const float*)d_in[4];  // (H)
    const float* W2    = (const float*)d_in[5];  // (K,H)
    const float* b2    = (const float*)d_in[6];  // (K)
    const float* convw = (const float*)d_in[7];  // (K,D)
    const float* convb = (const float*)d_in[8];  // (K)
    float* out = (float*)d_out;                  // [img_seg_score | joint_score]

    transpose_w2_kernel<<<dim3(32,4), dim3(32,8)>>>(W2);
    prep_kernel<<<80, 256>>>(img, lab, W1, b1, convw, convb, masks, out);
    joint_kernel<<<384, 256>>>(b2, out);
}

// round 10
// speedup vs baseline: 1.9473x; 1.9473x over previous
#include <cuda_runtime.h>
#include <cuda_bf16.h>
#include <cstdint>

// Problem constants
#define BB 2
#define TT 512
#define UU 48
#define DD 512
#define HH 1024
#define KK 128
#define SEG_ELEMS (BB*KK*TT)   // 131072 floats, first part of d_out

// Scratch (allocation-free rule: __device__ globals)
__device__ float g_img_pre[BB*TT*HH];           // [(b*T+t)][h] : img @ Wi^T (fp32)
__device__ float g_lab_pre[BB*UU*HH];           // [(b*U+u)][h] : lab @ Wl^T + b1 (fp32)
__device__ __nv_bfloat16 g_w2bf[KK*HH];         // W2 bf16, native (k,h) layout = B^T row-major

typedef unsigned long long u64;

__device__ __forceinline__ u64 pack2(float lo, float hi){
    u64 r; asm("mov.b64 %0, {%1, %2};" : "=l"(r) : "f"(lo), "f"(hi)); return r;
}
__device__ __forceinline__ void unpack2(u64 v, float& lo, float& hi){
    asm("mov.b64 {%0, %1}, %2;" : "=f"(lo), "=f"(hi) : "l"(v));
}
__device__ __forceinline__ void ffma2(u64& c, u64 a, u64 b){
    asm("fma.rn.f32x2 %0, %1, %2, %0;" : "+l"(c) : "l"(a), "l"(b));
}
__device__ __forceinline__ float tanh_hw(float x){
    asm("tanh.approx.f32 %0, %0;" : "+f"(x)); return x;
}
__device__ __forceinline__ uint32_t smem_u32(const void* p){
    uint32_t a;
    asm("{ .reg .u64 t; cvta.to.shared.u64 t, %1; cvt.u32.u64 %0, t; }" : "=r"(a) : "l"(p));
    return a;
}
// ldmatrix x4 (sm_75+, legal on plain sm_103 target)
__device__ __forceinline__ void ldsm_x4(uint32_t* r, uint32_t addr){
    asm volatile("ldmatrix.sync.aligned.m8n8.x4.shared.b16 {%0,%1,%2,%3}, [%4];"
        : "=r"(r[0]), "=r"(r[1]), "=r"(r[2]), "=r"(r[3]) : "r"(addr));
}
// mma.sync bf16 m16n8k16 (sm_80+, legal on plain sm_103 target)
__device__ __forceinline__ void mma16816(float* c, const uint32_t* a, uint32_t b0, uint32_t b1){
    asm volatile("mma.sync.aligned.m16n8k16.row.col.f32.bf16.bf16.f32 "
        "{%0,%1,%2,%3}, {%4,%5,%6,%7}, {%8,%9}, {%0,%1,%2,%3};"
        : "+f"(c[0]), "+f"(c[1]), "+f"(c[2]), "+f"(c[3])
        : "r"(a[0]), "r"(a[1]), "r"(a[2]), "r"(a[3]), "r"(b0), "r"(b1));
}
// SW128-style swizzled smem address (row = 128B)
__device__ __forceinline__ uint32_t sw_addr(uint32_t base, int row, int colb){
    uint32_t rel = (uint32_t)(row*128 + colb);
    return base + (rel ^ ((rel >> 3) & 0x70));
}

// ---------------------------------------------------------------------------
// W2 fp32 -> bf16 (layout preserved)
// ---------------------------------------------------------------------------
__global__ void convert_w2_kernel(const float* __restrict__ W2){
    int i = blockIdx.x*256 + threadIdx.x;   // 512 x 256 = 131072
    g_w2bf[i] = __float2bfloat16(W2[i]);
}

// ---------------------------------------------------------------------------
// Prep kernel (fp32 FFMA2): 3 NT-GEMMs, 80 CTAs one wave (unchanged from R7)
// ---------------------------------------------------------------------------
__global__ __launch_bounds__(256, 2) void prep_kernel(
    const float* __restrict__ img, const float* __restrict__ lab,
    const float* __restrict__ W1, const float* __restrict__ b1,
    const float* __restrict__ convw, const float* __restrict__ convb,
    const float* __restrict__ masks, float* __restrict__ out)
{
    __shared__ float As[128][16];
    __shared__ float Bs[16][132];

    int bx = blockIdx.x;
    const float* A; const float* Bp;
    int ldb, M, m0, n0, job;
    if (bx < 64)      { job=0; A=img; Bp=W1+DD; ldb=2*DD; M=BB*TT; m0=(bx&7)*128;  n0=(bx>>3)*128; }
    else if (bx < 72) { job=1; A=lab; Bp=W1;    ldb=2*DD; M=BB*UU; m0=0;           n0=(bx-64)*128; }
    else              { job=2; A=img; Bp=convw; ldb=DD;   M=BB*TT; m0=(bx-72)*128; n0=0; }

    int tid = threadIdx.x;
    int tx = tid & 15, ty = tid >> 4;
    int lm = tid >> 2, lq = (tid & 3) * 4;

    u64 c2[8][4];
    #pragma unroll
    for (int i = 0; i < 8; i++)
        #pragma unroll
        for (int j = 0; j < 4; j++) c2[i][j] = 0ull;

    for (int d0 = 0; d0 < DD; d0 += 16){
        int m1 = m0 + lm, m2 = m0 + lm + 64;
        float4 va1 = (m1 < M) ? *(const float4*)&A[m1*DD + d0 + lq] : make_float4(0,0,0,0);
        float4 va2 = (m2 < M) ? *(const float4*)&A[m2*DD + d0 + lq] : make_float4(0,0,0,0);
        float4 vb1 = *(const float4*)&Bp[(n0+lm)*ldb + d0 + lq];
        float4 vb2 = *(const float4*)&Bp[(n0+lm+64)*ldb + d0 + lq];
        *(float4*)&As[lm][lq]    = va1;
        *(float4*)&As[lm+64][lq] = va2;
        Bs[lq+0][lm] = vb1.x; Bs[lq+1][lm] = vb1.y; Bs[lq+2][lm] = vb1.z; Bs[lq+3][lm] = vb1.w;
        Bs[lq+0][lm+64] = vb2.x; Bs[lq+1][lm+64] = vb2.y; Bs[lq+2][lm+64] = vb2.z; Bs[lq+3][lm+64] = vb2.w;
        __syncthreads();
        #pragma unroll
        for (int dd = 0; dd < 16; dd++){
            u64 a2[8], bv[4];
            #pragma unroll
            for (int j = 0; j < 4; j++) bv[j] = *(const u64*)&Bs[dd][32*j + 2*tx];
            #pragma unroll
            for (int i = 0; i < 8; i++){ float av = As[ty + 16*i][dd]; a2[i] = pack2(av, av); }
            #pragma unroll
            for (int i = 0; i < 8; i++)
                #pragma unroll
                for (int j = 0; j < 4; j++) ffma2(c2[i][j], a2[i], bv[j]);
        }
        __syncthreads();
    }

    if (job == 0){
        #pragma unroll
        for (int i = 0; i < 8; i++){
            int m = m0 + ty + 16*i;
            #pragma unroll
            for (int j = 0; j < 4; j++){
                float lo, hi; unpack2(c2[i][j], lo, hi);
                *(float2*)&g_img_pre[m*HH + n0 + 32*j + 2*tx] = make_float2(lo, hi);
            }
        }
    } else if (job == 1){
        #pragma unroll
        for (int i = 0; i < 8; i++){
            int m = ty + 16*i;
            if (m < BB*UU){
                #pragma unroll
                for (int j = 0; j < 4; j++){
                    int n = n0 + 32*j + 2*tx;
                    float2 bb = *(const float2*)&b1[n];
                    float lo, hi; unpack2(c2[i][j], lo, hi);
                    *(float2*)&g_lab_pre[m*HH + n] = make_float2(lo + bb.x, hi + bb.y);
                }
            }
        }
    } else {
        #pragma unroll
        for (int i = 0; i < 8; i++){
            int m = m0 + ty + 16*i;
            float mk = masks[m];
            int b = m >> 9, t = m & 511;
            #pragma unroll
            for (int j = 0; j < 4; j++){
                int n = 32*j + 2*tx;
                float2 cb = *(const float2*)&convb[n];
                float lo, hi; unpack2(c2[i][j], lo, hi);
                out[(b*KK + n  )*TT + t] = (lo + cb.x)*mk;
                out[(b*KK + n+1)*TT + t] = (hi + cb.y)*mk;
            }
        }
    }
}

// ---------------------------------------------------------------------------
// Joint kernel: bf16 mma.sync (HMMA). C[t=128,k=128] = tanh(img_pre+lab_pre) @ W2^T
// then fused +b2 and log_softmax over k. 384 CTAs (96 pairs x 4 t-tiles),
// 8 warps = 4(m) x 2(n), each warp 32x64, fp32 accum in registers.
// ---------------------------------------------------------------------------
__global__ __launch_bounds__(256, 2)
void joint_mma_kernel(const float* __restrict__ b2, float* __restrict__ out)
{
    __shared__ __nv_bfloat16 Asm[128*64];   // 16KB, swizzled [t][h-chunk]
    __shared__ __nv_bfloat16 Bsm[128*64];   // 16KB, swizzled [k][h-chunk]
    __shared__ float b2s[KK];
    __shared__ float redmax[2][128];
    __shared__ float redsum[2][128];

    const int tid  = threadIdx.x;
    const int wid  = tid >> 5;
    const int lane = tid & 31;
    const int warp_m = wid & 3;     // 0..3 -> 32 t-rows each
    const int warp_n = wid >> 2;    // 0..1 -> 64 k-cols each
    const int lane4 = lane & 3;
    const int grp   = lane >> 2;

    const int pair = blockIdx.x >> 2;      // b*U+u
    const int t0   = (blockIdx.x & 3) * 128;
    const int b    = pair / UU;

    const uint32_t sbA = smem_u32(Asm);
    const uint32_t sbB = smem_u32(Bsm);

    if (tid < KK) b2s[tid] = b2[tid];

    const float* imgp = g_img_pre + (b*TT + t0)*HH;
    const float* labp = g_lab_pre + pair*HH;

    // staging role: row r (0..127), half hb (0 or 32 h-values)
    const int r  = tid >> 1;
    const int hb = (tid & 1) * 32;
    const uint32_t arel = (uint32_t)(r*128 + hb*2);   // bytes within tile

    float acc[2][8][4];
    #pragma unroll
    for (int mi = 0; mi < 2; mi++)
        #pragma unroll
        for (int ni = 0; ni < 8; ni++)
            #pragma unroll
            for (int j = 0; j < 4; j++) acc[mi][ni][j] = 0.f;

    for (int c = 0; c < 16; c++){
        const int h0 = c * 64;
        // ---- stage A: tanh(img_pre + lab_pre) -> bf16, swizzled ----
        {
            const float* ia = imgp + r*HH + h0 + hb;
            const float* la = labp + h0 + hb;
            float v[32];
            #pragma unroll
            for (int q = 0; q < 8; q++){
                float4 iv = *(const float4*)&ia[q*4];
                float4 lv = *(const float4*)&la[q*4];
                v[q*4+0] = tanh_hw(iv.x + lv.x);
                v[q*4+1] = tanh_hw(iv.y + lv.y);
                v[q*4+2] = tanh_hw(iv.z + lv.z);
                v[q*4+3] = tanh_hw(iv.w + lv.w);
            }
            #pragma unroll
            for (int j = 0; j < 4; j++){
                __nv_bfloat162 p0 = __floats2bfloat162_rn(v[j*8+0], v[j*8+1]);
                __nv_bfloat162 p1 = __floats2bfloat162_rn(v[j*8+2], v[j*8+3]);
                __nv_bfloat162 p2 = __floats2bfloat162_rn(v[j*8+4], v[j*8+5]);
                __nv_bfloat162 p3 = __floats2bfloat162_rn(v[j*8+6], v[j*8+7]);
                uint32_t rel = arel + j*16;
                uint32_t addr = sbA + (rel ^ ((rel >> 3) & 0x70));
                asm volatile("st.shared.v4.b32 [%0], {%1,%2,%3,%4};"
                    :: "r"(addr), "r"(*(uint32_t*)&p0), "r"(*(uint32_t*)&p1),
                       "r"(*(uint32_t*)&p2), "r"(*(uint32_t*)&p3));
            }
        }
        // ---- stage B: W2 bf16 chunk, swizzled ----
        {
            const uint4* wb = (const uint4*)(g_w2bf + r*HH + h0 + hb);
            #pragma unroll
            for (int j = 0; j < 4; j++){
                uint4 u = wb[j];
                uint32_t rel = arel + j*16;
                uint32_t addr = sbB + (rel ^ ((rel >> 3) & 0x70));
                asm volatile("st.shared.v4.b32 [%0], {%1,%2,%3,%4};"
                    :: "r"(addr), "r"(u.x), "r"(u.y), "r"(u.z), "r"(u.w));
            }
        }
        __syncthreads();

        // ---- 4 k16-steps of HMMA ----
        #pragma unroll
        for (int kk = 0; kk < 4; kk++){
            const int colb = kk*32 + (lane >> 4)*16;
            uint32_t af[2][4];
            #pragma unroll
            for (int mi = 0; mi < 2; mi++)
                ldsm_x4(af[mi], sw_addr(sbA, warp_m*32 + mi*16 + (lane & 15), colb));
            uint32_t bf[4][4];
            #pragma unroll
            for (int p = 0; p < 4; p++)
                ldsm_x4(bf[p], sw_addr(sbB, warp_n*64 + p*16 + (lane & 15), colb));
            #pragma unroll
            for (int mi = 0; mi < 2; mi++)
                #pragma unroll
                for (int p = 0; p < 4; p++){
                    mma16816(acc[mi][2*p  ], af[mi], bf[p][0], bf[p][2]);
                    mma16816(acc[mi][2*p+1], af[mi], bf[p][1], bf[p][3]);
                }
        }
        __syncthreads();
    }

    // ---- epilogue: +b2, log_softmax over k (row split across 2 n-warps) ----
    #pragma unroll
    for (int ni = 0; ni < 8; ni++){
        float2 bv = *(const float2*)&b2s[warp_n*64 + ni*8 + 2*lane4];
        #pragma unroll
        for (int mi = 0; mi < 2; mi++){
            acc[mi][ni][0] += bv.x; acc[mi][ni][1] += bv.y;
            acc[mi][ni][2] += bv.x; acc[mi][ni][3] += bv.y;
        }
    }
    // per-thread row maxima (rows: warp_m*32 + mi*16 + grp, +8)
    float rm[2][2];
    #pragma unroll
    for (int mi = 0; mi < 2; mi++)
        #pragma unroll
        for (int h = 0; h < 2; h++){
            float m = -1e30f;
            #pragma unroll
            for (int ni = 0; ni < 8; ni++)
                m = fmaxf(m, fmaxf(acc[mi][ni][2*h], acc[mi][ni][2*h+1]));
            #pragma unroll
            for (int d = 1; d < 4; d <<= 1)
                m = fmaxf(m, __shfl_xor_sync(0xffffffffu, m, d));
            rm[mi][h] = m;
        }
    if (lane4 == 0){
        #pragma unroll
        for (int mi = 0; mi < 2; mi++)
            #pragma unroll
            for (int h = 0; h < 2; h++)
                redmax[warp_n][warp_m*32 + mi*16 + grp + 8*h] = rm[mi][h];
    }
    __syncthreads();
    float mx[2][2], sm[2][2];
    #pragma unroll
    for (int mi = 0; mi < 2; mi++)
        #pragma unroll
        for (int h = 0; h < 2; h++){
            int row = warp_m*32 + mi*16 + grp + 8*h;
            mx[mi][h] = fmaxf(redmax[0][row], redmax[1][row]);
            float s = 0.f;
            #pragma unroll
            for (int ni = 0; ni < 8; ni++)
                s += __expf(acc[mi][ni][2*h] - mx[mi][h]) + __expf(acc[mi][ni][2*h+1] - mx[mi][h]);
            #pragma unroll
            for (int d = 1; d < 4; d <<= 1)
                s += __shfl_xor_sync(0xffffffffu, s, d);
            sm[mi][h] = s;
        }
    if (lane4 == 0){
        #pragma unroll
        for (int mi = 0; mi < 2; mi++)
            #pragma unroll
            for (int h = 0; h < 2; h++)
                redsum[warp_n][warp_m*32 + mi*16 + grp + 8*h] = sm[mi][h];
    }
    __syncthreads();
    float* outj = out + SEG_ELEMS + (pair*TT + t0)*KK;
    #pragma unroll
    for (int mi = 0; mi < 2; mi++)
        #pragma unroll
        for (int h = 0; h < 2; h++){
            int row = warp_m*32 + mi*16 + grp + 8*h;
            float L = mx[mi][h] + __logf(redsum[0][row] + redsum[1][row]);
            float* orow = outj + row*KK + warp_n*64;
            #pragma unroll
            for (int ni = 0; ni < 8; ni++)
                *(float2*)&orow[ni*8 + 2*lane4] =
                    make_float2(acc[mi][ni][2*h] - L, acc[mi][ni][2*h+1] - L);
        }
}

// ---------------------------------------------------------------------------
extern "C" void kernel_launch(void* const* d_in, const int* in_sizes, int n_in,
                              void* d_out, int out_size)
{
    (void)in_sizes; (void)n_in; (void)out_size;
    const float* img   = (const float*)d_in[0];  // (B,T,D)
    const float* lab   = (const float*)d_in[1];  // (B,U,D)
    const float* masks = (const float*)d_in[2];  // (B,1,T)
    const float* W1    = (const float*)d_in[3];  // (H,2D)
    const float* b1    = (const float*)d_in[4];  // (H)
    const float* W2    = (const float*)d_in[5];  // (K,H)
    const float* b2    = (const float*)d_in[6];  // (K)
    const float* convw = (const float*)d_in[7];  // (K,D)
    const float* convb = (const float*)d_in[8];  // (K)
    float* out = (float*)d_out;

    convert_w2_kernel<<<512, 256>>>(W2);
    prep_kernel<<<80, 256>>>(img, lab, W1, b1, convw, convb, masks, out);
    joint_mma_kernel<<<384, 256>>>(b2, out);
}

// round 11
// speedup vs baseline: 2.1442x; 1.1011x over previous
#include <cuda_runtime.h>
#include <cuda_bf16.h>
#include <cstdint>

// Problem constants
#define BB 2
#define TT 512
#define UU 48
#define DD 512
#define HH 1024
#define KK 128
#define SEG_ELEMS (BB*KK*TT)   // 131072 floats, first part of d_out

// Scratch (allocation-free rule: __device__ globals)
__device__ float g_img_pre[BB*TT*HH];           // [(b*T+t)][h] : img @ Wi^T (fp32)
__device__ float g_lab_pre[BB*UU*HH];           // [(b*U+u)][h] : lab @ Wl^T + b1 (fp32)
__device__ __nv_bfloat16 g_w2bf[KK*HH];         // W2 bf16, native (k,h) layout = B^T row-major

typedef unsigned long long u64;

__device__ __forceinline__ u64 pack2(float lo, float hi){
    u64 r; asm("mov.b64 %0, {%1, %2};" : "=l"(r) : "f"(lo), "f"(hi)); return r;
}
__device__ __forceinline__ void unpack2(u64 v, float& lo, float& hi){
    asm("mov.b64 {%0, %1}, %2;" : "=f"(lo), "=f"(hi) : "l"(v));
}
__device__ __forceinline__ void ffma2(u64& c, u64 a, u64 b){
    asm("fma.rn.f32x2 %0, %1, %2, %0;" : "+l"(c) : "l"(a), "l"(b));
}
__device__ __forceinline__ float tanh_hw(float x){
    asm("tanh.approx.f32 %0, %0;" : "+f"(x)); return x;
}
__device__ __forceinline__ uint32_t smem_u32(const void* p){
    uint32_t a;
    asm("{ .reg .u64 t; cvta.to.shared.u64 t, %1; cvt.u32.u64 %0, t; }" : "=r"(a) : "l"(p));
    return a;
}
__device__ __forceinline__ void ldsm_x4(uint32_t* r, uint32_t addr){
    asm volatile("ldmatrix.sync.aligned.m8n8.x4.shared.b16 {%0,%1,%2,%3}, [%4];"
        : "=r"(r[0]), "=r"(r[1]), "=r"(r[2]), "=r"(r[3]) : "r"(addr));
}
__device__ __forceinline__ void mma16816(float* c, const uint32_t* a, uint32_t b0, uint32_t b1){
    asm volatile("mma.sync.aligned.m16n8k16.row.col.f32.bf16.bf16.f32 "
        "{%0,%1,%2,%3}, {%4,%5,%6,%7}, {%8,%9}, {%0,%1,%2,%3};"
        : "+f"(c[0]), "+f"(c[1]), "+f"(c[2]), "+f"(c[3])
        : "r"(a[0]), "r"(a[1]), "r"(a[2]), "r"(a[3]), "r"(b0), "r"(b1));
}
__device__ __forceinline__ uint32_t sw_addr(uint32_t base, int row, int colb){
    uint32_t rel = (uint32_t)(row*128 + colb);
    return base + (rel ^ ((rel >> 3) & 0x70));
}
__device__ __forceinline__ void cp_async16(uint32_t dst, const void* src){
    asm volatile("cp.async.cg.shared.global [%0], [%1], 16;" :: "r"(dst), "l"(src));
}
__device__ __forceinline__ void cp_commit(){ asm volatile("cp.async.commit_group;" ::: "memory"); }
__device__ __forceinline__ void cp_wait0(){ asm volatile("cp.async.wait_group 0;" ::: "memory"); }

// ---------------------------------------------------------------------------
// Prep kernel (fp32 FFMA2): 3 NT-GEMMs + W2 bf16 convert, 88 CTAs one wave
// ---------------------------------------------------------------------------
__global__ __launch_bounds__(256, 2) void prep_kernel(
    const float* __restrict__ img, const float* __restrict__ lab,
    const float* __restrict__ W1, const float* __restrict__ b1,
    const float* __restrict__ convw, const float* __restrict__ convb,
    const float* __restrict__ masks, const float* __restrict__ W2,
    float* __restrict__ out)
{
    __shared__ float As[128][16];
    __shared__ float Bs[16][132];

    int bx = blockIdx.x;
    int tid = threadIdx.x;

    if (bx >= 80){
        // W2 fp32 -> bf16 convert: blocks 80..87, 16384 elems each
        int base = (bx - 80)*16384 + tid*4;
        #pragma unroll
        for (int q = 0; q < 16; q++){
            int i = base + q*1024;
            float4 wv = *(const float4*)&W2[i];
            __nv_bfloat162 p0 = __floats2bfloat162_rn(wv.x, wv.y);
            __nv_bfloat162 p1 = __floats2bfloat162_rn(wv.z, wv.w);
            uint2 u; u.x = *(uint32_t*)&p0; u.y = *(uint32_t*)&p1;
            *(uint2*)&g_w2bf[i] = u;
        }
        return;
    }

    const float* A; const float* Bp;
    int ldb, M, m0, n0, job;
    if (bx < 64)      { job=0; A=img; Bp=W1+DD; ldb=2*DD; M=BB*TT; m0=(bx&7)*128;  n0=(bx>>3)*128; }
    else if (bx < 72) { job=1; A=lab; Bp=W1;    ldb=2*DD; M=BB*UU; m0=0;           n0=(bx-64)*128; }
    else              { job=2; A=img; Bp=convw; ldb=DD;   M=BB*TT; m0=(bx-72)*128; n0=0; }

    int tx = tid & 15, ty = tid >> 4;
    int lm = tid >> 2, lq = (tid & 3) * 4;

    u64 c2[8][4];
    #pragma unroll
    for (int i = 0; i < 8; i++)
        #pragma unroll
        for (int j = 0; j < 4; j++) c2[i][j] = 0ull;

    for (int d0 = 0; d0 < DD; d0 += 16){
        int m1 = m0 + lm, m2 = m0 + lm + 64;
        float4 va1 = (m1 < M) ? *(const float4*)&A[m1*DD + d0 + lq] : make_float4(0,0,0,0);
        float4 va2 = (m2 < M) ? *(const float4*)&A[m2*DD + d0 + lq] : make_float4(0,0,0,0);
        float4 vb1 = *(const float4*)&Bp[(n0+lm)*ldb + d0 + lq];
        float4 vb2 = *(const float4*)&Bp[(n0+lm+64)*ldb + d0 + lq];
        *(float4*)&As[lm][lq]    = va1;
        *(float4*)&As[lm+64][lq] = va2;
        Bs[lq+0][lm] = vb1.x; Bs[lq+1][lm] = vb1.y; Bs[lq+2][lm] = vb1.z; Bs[lq+3][lm] = vb1.w;
        Bs[lq+0][lm+64] = vb2.x; Bs[lq+1][lm+64] = vb2.y; Bs[lq+2][lm+64] = vb2.z; Bs[lq+3][lm+64] = vb2.w;
        __syncthreads();
        #pragma unroll
        for (int dd = 0; dd < 16; dd++){
            u64 a2[8], bv[4];
            #pragma unroll
            for (int j = 0; j < 4; j++) bv[j] = *(const u64*)&Bs[dd][32*j + 2*tx];
            #pragma unroll
            for (int i = 0; i < 8; i++){ float av = As[ty + 16*i][dd]; a2[i] = pack2(av, av); }
            #pragma unroll
            for (int i = 0; i < 8; i++)
                #pragma unroll
                for (int j = 0; j < 4; j++) ffma2(c2[i][j], a2[i], bv[j]);
        }
        __syncthreads();
    }

    if (job == 0){
        #pragma unroll
        for (int i = 0; i < 8; i++){
            int m = m0 + ty + 16*i;
            #pragma unroll
            for (int j = 0; j < 4; j++){
                float lo, hi; unpack2(c2[i][j], lo, hi);
                *(float2*)&g_img_pre[m*HH + n0 + 32*j + 2*tx] = make_float2(lo, hi);
            }
        }
    } else if (job == 1){
        #pragma unroll
        for (int i = 0; i < 8; i++){
            int m = ty + 16*i;
            if (m < BB*UU){
                #pragma unroll
                for (int j = 0; j < 4; j++){
                    int n = n0 + 32*j + 2*tx;
                    float2 bb = *(const float2*)&b1[n];
                    float lo, hi; unpack2(c2[i][j], lo, hi);
                    *(float2*)&g_lab_pre[m*HH + n] = make_float2(lo + bb.x, hi + bb.y);
                }
            }
        }
    } else {
        #pragma unroll
        for (int i = 0; i < 8; i++){
            int m = m0 + ty + 16*i;
            float mk = masks[m];
            int b = m >> 9, t = m & 511;
            #pragma unroll
            for (int j = 0; j < 4; j++){
                int n = 32*j + 2*tx;
                float2 cb = *(const float2*)&convb[n];
                float lo, hi; unpack2(c2[i][j], lo, hi);
                out[(b*KK + n  )*TT + t] = (lo + cb.x)*mk;
                out[(b*KK + n+1)*TT + t] = (hi + cb.y)*mk;
            }
        }
    }
}

// ---------------------------------------------------------------------------
// Joint kernel: double-buffered bf16 HMMA pipeline.
// C[t=128,k=128] = tanh(img_pre+lab_pre) @ W2^T, fused +b2 + log_softmax(k).
// 384 CTAs (96 pairs x 4 t-tiles); 8 warps = 4(m) x 2(n), 32x64 per warp.
// Per chunk: cp.async B(c+1), LDG A(c+1) -> MMA(c) -> tanh/store A(c+1); 1 sync.
// ---------------------------------------------------------------------------
#define JSM_A0   0u
#define JSM_A1   16384u
#define JSM_B0   32768u
#define JSM_B1   49152u
#define JSM_B2S  65536u
#define JSM_RM   66048u   // 2*128 floats
#define JSM_RS   67072u
#define JSM_TOTAL 68096

__global__ __launch_bounds__(256, 2)
void joint_mma_kernel(const float* __restrict__ b2, float* __restrict__ out)
{
    extern __shared__ char dsm[];
    const uint32_t sb = smem_u32(dsm);
    float* b2s  = (float*)(dsm + JSM_B2S);
    float* redm = (float*)(dsm + JSM_RM);
    float* reds = (float*)(dsm + JSM_RS);

    const int tid  = threadIdx.x;
    const int wid  = tid >> 5;
    const int lane = tid & 31;
    const int warp_m = wid & 3;
    const int warp_n = wid >> 2;
    const int lane4 = lane & 3;
    const int grp   = lane >> 2;

    const int pair = blockIdx.x >> 2;
    const int t0   = (blockIdx.x & 3) * 128;
    const int b    = pair / UU;

    if (tid < KK) b2s[tid] = b2[tid];

    const float* imgp = g_img_pre + (b*TT + t0)*HH;
    const float* labp = g_lab_pre + pair*HH;

    // staging role: row r (0..127), half hb (0 or 32 h-values)
    const int r  = tid >> 1;
    const int hb = (tid & 1) * 32;
    const uint32_t arel = (uint32_t)(r*128 + hb*2);  // bytes within a tile

    float acc[2][8][4];
    #pragma unroll
    for (int mi = 0; mi < 2; mi++)
        #pragma unroll
        for (int ni = 0; ni < 8; ni++)
            #pragma unroll
            for (int j = 0; j < 4; j++) acc[mi][ni][j] = 0.f;

    // -------- prologue: stage chunk 0 into buffer 0 --------
    {
        const char* wsrc = (const char*)(g_w2bf + r*HH + hb);
        #pragma unroll
        for (int j = 0; j < 4; j++){
            uint32_t rel = arel + j*16;
            cp_async16(sb + JSM_B0 + (rel ^ ((rel >> 3) & 0x70)), wsrc + j*16);
        }
        cp_commit();
        const float* ia = imgp + r*HH + hb;
        const float* la = labp + hb;
        float v[32];
        #pragma unroll
        for (int q = 0; q < 8; q++){
            float4 iv = *(const float4*)&ia[q*4];
            float4 lv = *(const float4*)&la[q*4];
            v[q*4+0] = tanh_hw(iv.x + lv.x);
            v[q*4+1] = tanh_hw(iv.y + lv.y);
            v[q*4+2] = tanh_hw(iv.z + lv.z);
            v[q*4+3] = tanh_hw(iv.w + lv.w);
        }
        #pragma unroll
        for (int j = 0; j < 4; j++){
            __nv_bfloat162 p0 = __floats2bfloat162_rn(v[j*8+0], v[j*8+1]);
            __nv_bfloat162 p1 = __floats2bfloat162_rn(v[j*8+2], v[j*8+3]);
            __nv_bfloat162 p2 = __floats2bfloat162_rn(v[j*8+4], v[j*8+5]);
            __nv_bfloat162 p3 = __floats2bfloat162_rn(v[j*8+6], v[j*8+7]);
            uint32_t rel = arel + j*16;
            uint32_t addr = sb + JSM_A0 + (rel ^ ((rel >> 3) & 0x70));
            asm volatile("st.shared.v4.b32 [%0], {%1,%2,%3,%4};"
                :: "r"(addr), "r"(*(uint32_t*)&p0), "r"(*(uint32_t*)&p1),
                   "r"(*(uint32_t*)&p2), "r"(*(uint32_t*)&p3));
        }
        cp_wait0();
    }
    __syncthreads();

    // -------- main pipelined loop --------
    for (int c = 0; c < 16; c++){
        const int s = c & 1;
        const int hn = c*64 + 64;               // next chunk's h base
        float pre[32];

        if (c < 15){
            // B(c+1): async copy into the other buffer
            const char* wsrc = (const char*)(g_w2bf + r*HH + hn + hb);
            const uint32_t bnext = sb + (s ? JSM_B0 : JSM_B1);
            #pragma unroll
            for (int j = 0; j < 4; j++){
                uint32_t rel = arel + j*16;
                cp_async16(bnext + (rel ^ ((rel >> 3) & 0x70)), wsrc + j*16);
            }
            cp_commit();
            // A(c+1): prefetch gmem into registers (latency hidden by MMA below)
            const float* ia = imgp + r*HH + hn + hb;
            #pragma unroll
            for (int q = 0; q < 8; q++)
                *(float4*)&pre[q*4] = *(const float4*)&ia[q*4];
        }

        // ---- MMA on buffer s ----
        {
            const uint32_t Ab = sb + (s ? JSM_A1 : JSM_A0);
            const uint32_t Bb = sb + (s ? JSM_B1 : JSM_B0);
            #pragma unroll
            for (int kk = 0; kk < 4; kk++){
                const int colb = kk*32 + (lane >> 4)*16;
                uint32_t af[2][4];
                #pragma unroll
                for (int mi = 0; mi < 2; mi++)
                    ldsm_x4(af[mi], sw_addr(Ab, warp_m*32 + mi*16 + (lane & 15), colb));
                uint32_t bf[4][4];
                #pragma unroll
                for (int p = 0; p < 4; p++)
                    ldsm_x4(bf[p], sw_addr(Bb, warp_n*64 + p*16 + (lane & 15), colb));
                #pragma unroll
                for (int mi = 0; mi < 2; mi++)
                    #pragma unroll
                    for (int p = 0; p < 4; p++){
                        mma16816(acc[mi][2*p  ], af[mi], bf[p][0], bf[p][2]);
                        mma16816(acc[mi][2*p+1], af[mi], bf[p][1], bf[p][3]);
                    }
            }
        }

        if (c < 15){
            // finish A(c+1): tanh, cvt, swizzled store into the other buffer
            const float* la = labp + hn + hb;
            const uint32_t anext = sb + (s ? JSM_A0 : JSM_A1);
            #pragma unroll
            for (int q = 0; q < 8; q++){
                float4 lv = *(const float4*)&la[q*4];
                pre[q*4+0] = tanh_hw(pre[q*4+0] + lv.x);
                pre[q*4+1] = tanh_hw(pre[q*4+1] + lv.y);
                pre[q*4+2] = tanh_hw(pre[q*4+2] + lv.z);
                pre[q*4+3] = tanh_hw(pre[q*4+3] + lv.w);
            }
            #pragma unroll
            for (int j = 0; j < 4; j++){
                __nv_bfloat162 p0 = __floats2bfloat162_rn(pre[j*8+0], pre[j*8+1]);
                __nv_bfloat162 p1 = __floats2bfloat162_rn(pre[j*8+2], pre[j*8+3]);
                __nv_bfloat162 p2 = __floats2bfloat162_rn(pre[j*8+4], pre[j*8+5]);
                __nv_bfloat162 p3 = __floats2bfloat162_rn(pre[j*8+6], pre[j*8+7]);
                uint32_t rel = arel + j*16;
                uint32_t addr = anext + (rel ^ ((rel >> 3) & 0x70));
                asm volatile("st.shared.v4.b32 [%0], {%1,%2,%3,%4};"
                    :: "r"(addr), "r"(*(uint32_t*)&p0), "r"(*(uint32_t*)&p1),
                       "r"(*(uint32_t*)&p2), "r"(*(uint32_t*)&p3));
            }
            cp_wait0();
        }
        __syncthreads();
    }

    // ---- epilogue: +b2, log_softmax over k (row split across 2 n-warps) ----
    #pragma unroll
    for (int ni = 0; ni < 8; ni++){
        float2 bv = *(const float2*)&b2s[warp_n*64 + ni*8 + 2*lane4];
        #pragma unroll
        for (int mi = 0; mi < 2; mi++){
            acc[mi][ni][0] += bv.x; acc[mi][ni][1] += bv.y;
            acc[mi][ni][2] += bv.x; acc[mi][ni][3] += bv.y;
        }
    }
    float rm[2][2];
    #pragma unroll
    for (int mi = 0; mi < 2; mi++)
        #pragma unroll
        for (int h = 0; h < 2; h++){
            float m = -1e30f;
            #pragma unroll
            for (int ni = 0; ni < 8; ni++)
                m = fmaxf(m, fmaxf(acc[mi][ni][2*h], acc[mi][ni][2*h+1]));
            #pragma unroll
            for (int d = 1; d < 4; d <<= 1)
                m = fmaxf(m, __shfl_xor_sync(0xffffffffu, m, d));
            rm[mi][h] = m;
        }
    if (lane4 == 0){
        #pragma unroll
        for (int mi = 0; mi < 2; mi++)
            #pragma unroll
            for (int h = 0; h < 2; h++)
                redm[warp_n*128 + warp_m*32 + mi*16 + grp + 8*h] = rm[mi][h];
    }
    __syncthreads();
    float mx[2][2], sm[2][2];
    #pragma unroll
    for (int mi = 0; mi < 2; mi++)
        #pragma unroll
        for (int h = 0; h < 2; h++){
            int row = warp_m*32 + mi*16 + grp + 8*h;
            mx[mi][h] = fmaxf(redm[row], redm[128 + row]);
            float s = 0.f;
            #pragma unroll
            for (int ni = 0; ni < 8; ni++)
                s += __expf(acc[mi][ni][2*h] - mx[mi][h]) + __expf(acc[mi][ni][2*h+1] - mx[mi][h]);
            #pragma unroll
            for (int d = 1; d < 4; d <<= 1)
                s += __shfl_xor_sync(0xffffffffu, s, d);
            sm[mi][h] = s;
        }
    if (lane4 == 0){
        #pragma unroll
        for (int mi = 0; mi < 2; mi++)
            #pragma unroll
            for (int h = 0; h < 2; h++)
                reds[warp_n*128 + warp_m*32 + mi*16 + grp + 8*h] = sm[mi][h];
    }
    __syncthreads();
    float* outj = out + SEG_ELEMS + (pair*TT + t0)*KK;
    #pragma unroll
    for (int mi = 0; mi < 2; mi++)
        #pragma unroll
        for (int h = 0; h < 2; h++){
            int row = warp_m*32 + mi*16 + grp + 8*h;
            float L = mx[mi][h] + __logf(reds[row] + reds[128 + row]);
            float* orow = outj + row*KK + warp_n*64;
            #pragma unroll
            for (int ni = 0; ni < 8; ni++)
                *(float2*)&orow[ni*8 + 2*lane4] =
                    make_float2(acc[mi][ni][2*h] - L, acc[mi][ni][2*h+1] - L);
        }
}

// ---------------------------------------------------------------------------
extern "C" void kernel_launch(void* const* d_in, const int* in_sizes, int n_in,
                              void* d_out, int out_size)
{
    (void)in_sizes; (void)n_in; (void)out_size;
    const float* img   = (const float*)d_in[0];  // (B,T,D)
    const float* lab   = (const float*)d_in[1];  // (B,U,D)
    const float* masks = (const float*)d_in[2];  // (B,1,T)
    const float* W1    = (const float*)d_in[3];  // (H,2D)
    const float* b1    = (const float*)d_in[4];  // (H)
    const float* W2    = (const float*)d_in[5];  // (K,H)
    const float* b2    = (const float*)d_in[6];  // (K)
    const float* convw = (const float*)d_in[7];  // (K,D)
    const float* convb = (const float*)d_in[8];  // (K)
    float* out = (float*)d_out;

    cudaFuncSetAttribute(joint_mma_kernel,
                         cudaFuncAttributeMaxDynamicSharedMemorySize, JSM_TOTAL);

    prep_kernel<<<88, 256>>>(img, lab, W1, b1, convw, convb, masks, W2, out);
    joint_mma_kernel<<<384, 256, JSM_TOTAL>>>(b2, out);
}

// round 12
// speedup vs baseline: 2.7131x; 1.2653x over previous
#include <cuda_runtime.h>
#include <cuda_bf16.h>
#include <cstdint>

// Problem constants
#define BB 2
#define TT 512
#define UU 48
#define DD 512
#define HH 1024
#define KK 128
#define SEG_ELEMS (BB*KK*TT)   // 131072 floats, first part of d_out

// Scratch (allocation-free rule: __device__ globals)
__device__ float g_img_pre[BB*TT*HH];           // [(b*T+t)][h] : img @ Wi^T (fp32)
__device__ float g_lab_pre[BB*UU*HH];           // [(b*U+u)][h] : lab @ Wl^T + b1 (fp32)
__device__ __nv_bfloat16 g_w2bf[KK*HH];         // W2 bf16, native (k,h) layout = B^T row-major

__device__ __forceinline__ float tanh_hw(float x){
    asm("tanh.approx.f32 %0, %0;" : "+f"(x)); return x;
}
__device__ __forceinline__ uint32_t smem_u32(const void* p){
    uint32_t a;
    asm("{ .reg .u64 t; cvta.to.shared.u64 t, %1; cvt.u32.u64 %0, t; }" : "=r"(a) : "l"(p));
    return a;
}
__device__ __forceinline__ void ldsm_x4(uint32_t* r, uint32_t addr){
    asm volatile("ldmatrix.sync.aligned.m8n8.x4.shared.b16 {%0,%1,%2,%3}, [%4];"
        : "=r"(r[0]), "=r"(r[1]), "=r"(r[2]), "=r"(r[3]) : "r"(addr));
}
__device__ __forceinline__ void mma16816(float* c, const uint32_t* a, uint32_t b0, uint32_t b1){
    asm volatile("mma.sync.aligned.m16n8k16.row.col.f32.bf16.bf16.f32 "
        "{%0,%1,%2,%3}, {%4,%5,%6,%7}, {%8,%9}, {%0,%1,%2,%3};"
        : "+f"(c[0]), "+f"(c[1]), "+f"(c[2]), "+f"(c[3])
        : "r"(a[0]), "r"(a[1]), "r"(a[2]), "r"(a[3]), "r"(b0), "r"(b1));
}
__device__ __forceinline__ void mma1688_tf32(float* c, const uint32_t* a, uint32_t b0, uint32_t b1){
    asm volatile("mma.sync.aligned.m16n8k8.row.col.f32.tf32.tf32.f32 "
        "{%0,%1,%2,%3}, {%4,%5,%6,%7}, {%8,%9}, {%0,%1,%2,%3};"
        : "+f"(c[0]), "+f"(c[1]), "+f"(c[2]), "+f"(c[3])
        : "r"(a[0]), "r"(a[1]), "r"(a[2]), "r"(a[3]), "r"(b0), "r"(b1));
}
__device__ __forceinline__ uint32_t sw_addr(uint32_t base, int row, int colb){
    uint32_t rel = (uint32_t)(row*128 + colb);
    return base + (rel ^ ((rel >> 3) & 0x70));
}
__device__ __forceinline__ void cp_async16(uint32_t dst, const void* src){
    asm volatile("cp.async.cg.shared.global [%0], [%1], 16;" :: "r"(dst), "l"(src));
}
__device__ __forceinline__ void cp_commit(){ asm volatile("cp.async.commit_group;" ::: "memory"); }
__device__ __forceinline__ void cp_wait0(){ asm volatile("cp.async.wait_group 0;" ::: "memory"); }
__device__ __forceinline__ uint32_t f2tf32(float x){
    uint32_t r; asm("cvt.rna.tf32.f32 %0, %1;" : "=r"(r) : "f"(x)); return r;
}
__device__ __forceinline__ float lds32(uint32_t addr){
    float v; asm volatile("ld.shared.f32 %0, [%1];" : "=f"(v) : "r"(addr)); return v;
}

// ---------------------------------------------------------------------------
// Prep kernel, tf32 tensor-core: 3 NT-GEMMs + W2 bf16 convert. 88 CTAs.
//   job0 (0..63):  img_pre = img @ Wi^T          (1024x1024, k=512)
//   job1 (64..71): lab_pre = lab @ Wl^T + b1     (96x1024)
//   job2 (72..79): seg = (img @ conv_w^T + cb)*m (1024x128), transposed store
//   bx>=80: W2 fp32->bf16
// 128x128 tile, 8 warps (4m x 2n), warp 32x64, m16n8k8 tf32, fp32 accum.
// Double-buffered swizzled smem; per-kstep interleaved LDG->cvt.rna->STS.
// ---------------------------------------------------------------------------
#define PSM_A0 0u
#define PSM_A1 16384u
#define PSM_B0 32768u
#define PSM_B1 49152u
#define PSM_TOTAL 65536

__global__ __launch_bounds__(256, 2) void prep_tc_kernel(
    const float* __restrict__ img, const float* __restrict__ lab,
    const float* __restrict__ W1, const float* __restrict__ b1,
    const float* __restrict__ convw, const float* __restrict__ convb,
    const float* __restrict__ masks, const float* __restrict__ W2,
    float* __restrict__ out)
{
    extern __shared__ char dsm[];
    const int bx  = blockIdx.x;
    const int tid = threadIdx.x;

    if (bx >= 80){
        // W2 fp32 -> bf16 convert: blocks 80..87, 16384 elems each
        int base = (bx - 80)*16384 + tid*4;
        #pragma unroll
        for (int q = 0; q < 16; q++){
            int i = base + q*1024;
            float4 wv = *(const float4*)&W2[i];
            __nv_bfloat162 p0 = __floats2bfloat162_rn(wv.x, wv.y);
            __nv_bfloat162 p1 = __floats2bfloat162_rn(wv.z, wv.w);
            uint2 u; u.x = *(uint32_t*)&p0; u.y = *(uint32_t*)&p1;
            *(uint2*)&g_w2bf[i] = u;
        }
        return;
    }

    const uint32_t sb = smem_u32(dsm);
    const float* A; const float* Bp;
    int ldb, M, m0, n0, job;
    if (bx < 64)      { job=0; A=img; Bp=W1+DD; ldb=2*DD; M=BB*TT; m0=(bx&7)*128;  n0=(bx>>3)*128; }
    else if (bx < 72) { job=1; A=lab; Bp=W1;    ldb=2*DD; M=BB*UU; m0=0;           n0=(bx-64)*128; }
    else              { job=2; A=img; Bp=convw; ldb=DD;   M=BB*TT; m0=(bx-72)*128; n0=0; }

    const int wid  = tid >> 5;
    const int lane = tid & 31;
    const int warp_m = wid & 3;     // 32 m-rows
    const int warp_n = wid >> 2;    // 64 n-cols
    const int lane4 = lane & 3;
    const int grp   = lane >> 2;

    // staging role: row r, half: cols half*16..+16 (floats)
    const int r    = tid >> 1;
    const int cb0  = (tid & 1) * 16;
    const bool avalid = (m0 + r) < M;
    const float* arow = A  + (size_t)(m0 + r)*DD;
    const float* brow = Bp + (size_t)(n0 + r)*ldb;

    float acc[2][8][4];
    #pragma unroll
    for (int mi = 0; mi < 2; mi++)
        #pragma unroll
        for (int ni = 0; ni < 8; ni++)
            #pragma unroll
            for (int j = 0; j < 4; j++) acc[mi][ni][j] = 0.f;

    // prologue: stage chunk 0 into buffer 0
    #pragma unroll
    for (int kk = 0; kk < 4; kk++){
        int col = cb0 + kk*4;
        float4 av = avalid ? *(const float4*)&arow[col] : make_float4(0,0,0,0);
        float4 bv = *(const float4*)&brow[col];
        uint4 at, bt;
        at.x = f2tf32(av.x); at.y = f2tf32(av.y); at.z = f2tf32(av.z); at.w = f2tf32(av.w);
        bt.x = f2tf32(bv.x); bt.y = f2tf32(bv.y); bt.z = f2tf32(bv.z); bt.w = f2tf32(bv.w);
        uint32_t aa = sw_addr(sb + PSM_A0, r, col*4);
        uint32_t ba = sw_addr(sb + PSM_B0, r, col*4);
        asm volatile("st.shared.v4.b32 [%0], {%1,%2,%3,%4};"
            :: "r"(aa), "r"(at.x), "r"(at.y), "r"(at.z), "r"(at.w));
        asm volatile("st.shared.v4.b32 [%0], {%1,%2,%3,%4};"
            :: "r"(ba), "r"(bt.x), "r"(bt.y), "r"(bt.z), "r"(bt.w));
    }
    __syncthreads();

    for (int c = 0; c < 16; c++){
        const int s  = c & 1;
        const int dn = c*32 + 32;
        const uint32_t Ab = sb + (s ? PSM_A1 : PSM_A0);
        const uint32_t Bb = sb + (s ? PSM_B1 : PSM_B0);
        const uint32_t An = sb + (s ? PSM_A0 : PSM_A1);
        const uint32_t Bn = sb + (s ? PSM_B0 : PSM_B1);

        #pragma unroll
        for (int kk = 0; kk < 4; kk++){
            // prefetch next chunk's slice for this kstep
            float4 av, bv;
            if (c < 15){
                int col = dn + cb0 + kk*4;
                av = avalid ? *(const float4*)&arow[col] : make_float4(0,0,0,0);
                bv = *(const float4*)&brow[col];
            }
            // fragment loads (swizzled LDS.32, conflict-free) + mma
            const int ca = (kk*8 + lane4)*4;
            const int cc = (kk*8 + lane4 + 4)*4;
            uint32_t af[2][4];
            #pragma unroll
            for (int mi = 0; mi < 2; mi++){
                int rb = warp_m*32 + mi*16;
                af[mi][0] = __float_as_uint(lds32(sw_addr(Ab, rb + grp,     ca)));
                af[mi][1] = __float_as_uint(lds32(sw_addr(Ab, rb + grp + 8, ca)));
                af[mi][2] = __float_as_uint(lds32(sw_addr(Ab, rb + grp,     cc)));
                af[mi][3] = __float_as_uint(lds32(sw_addr(Ab, rb + grp + 8, cc)));
            }
            #pragma unroll
            for (int ni = 0; ni < 8; ni++){
                int rn = warp_n*64 + ni*8 + grp;
                uint32_t b0 = __float_as_uint(lds32(sw_addr(Bb, rn, ca)));
                uint32_t b1 = __float_as_uint(lds32(sw_addr(Bb, rn, cc)));
                mma1688_tf32(acc[0][ni], af[0], b0, b1);
                mma1688_tf32(acc[1][ni], af[1], b0, b1);
            }
            // stage prefetched slice into the other buffer
            if (c < 15){
                int col = cb0 + kk*4;
                uint4 at, bt;
                at.x = f2tf32(av.x); at.y = f2tf32(av.y); at.z = f2tf32(av.z); at.w = f2tf32(av.w);
                bt.x = f2tf32(bv.x); bt.y = f2tf32(bv.y); bt.z = f2tf32(bv.z); bt.w = f2tf32(bv.w);
                asm volatile("st.shared.v4.b32 [%0], {%1,%2,%3,%4};"
                    :: "r"(sw_addr(An, r, col*4)), "r"(at.x), "r"(at.y), "r"(at.z), "r"(at.w));
                asm volatile("st.shared.v4.b32 [%0], {%1,%2,%3,%4};"
                    :: "r"(sw_addr(Bn, r, col*4)), "r"(bt.x), "r"(bt.y), "r"(bt.z), "r"(bt.w));
            }
        }
        __syncthreads();
    }

    // ---- epilogue ----
    if (job == 0){
        #pragma unroll
        for (int mi = 0; mi < 2; mi++)
            #pragma unroll
            for (int h = 0; h < 2; h++){
                int m = m0 + warp_m*32 + mi*16 + grp + 8*h;
                float* orow = g_img_pre + (size_t)m*HH + n0 + warp_n*64;
                #pragma unroll
                for (int ni = 0; ni < 8; ni++)
                    *(float2*)&orow[ni*8 + 2*lane4] =
                        make_float2(acc[mi][ni][2*h], acc[mi][ni][2*h+1]);
            }
    } else if (job == 1){
        #pragma unroll
        for (int mi = 0; mi < 2; mi++)
            #pragma unroll
            for (int h = 0; h < 2; h++){
                int m = warp_m*32 + mi*16 + grp + 8*h;
                if (m < BB*UU){
                    float* orow = g_lab_pre + (size_t)m*HH + n0 + warp_n*64;
                    #pragma unroll
                    for (int ni = 0; ni < 8; ni++){
                        int n = ni*8 + 2*lane4;
                        float2 bb = *(const float2*)&b1[n0 + warp_n*64 + n];
                        *(float2*)&orow[n] =
                            make_float2(acc[mi][ni][2*h] + bb.x, acc[mi][ni][2*h+1] + bb.y);
                    }
                }
            }
    } else {
        #pragma unroll
        for (int mi = 0; mi < 2; mi++)
            #pragma unroll
            for (int h = 0; h < 2; h++){
                int m = m0 + warp_m*32 + mi*16 + grp + 8*h;
                float mk = masks[m];
                int b = m >> 9, t = m & 511;
                #pragma unroll
                for (int ni = 0; ni < 8; ni++){
                    int n = warp_n*64 + ni*8 + 2*lane4;
                    float2 cbv = *(const float2*)&convb[n];
                    out[(b*KK + n  )*TT + t] = (acc[mi][ni][2*h  ] + cbv.x)*mk;
                    out[(b*KK + n+1)*TT + t] = (acc[mi][ni][2*h+1] + cbv.y)*mk;
                }
            }
    }
}

// ---------------------------------------------------------------------------
// Joint kernel: double-buffered bf16 HMMA pipeline, per-kstep interleaved
// A prefetch (8 live regs instead of 32 -> no spills).
// C[t=128,k=128] = tanh(img_pre+lab_pre) @ W2^T, fused +b2 + log_softmax(k).
// 384 CTAs (96 pairs x 4 t-tiles); 8 warps = 4(m) x 2(n), 32x64 per warp.
// ---------------------------------------------------------------------------
#define JSM_A0   0u
#define JSM_A1   16384u
#define JSM_B0   32768u
#define JSM_B1   49152u
#define JSM_B2S  65536u
#define JSM_RM   66048u   // 2*128 floats
#define JSM_RS   67072u
#define JSM_TOTAL 68096

__global__ __launch_bounds__(256, 2)
void joint_mma_kernel(const float* __restrict__ b2, float* __restrict__ out)
{
    extern __shared__ char dsm[];
    const uint32_t sb = smem_u32(dsm);
    float* b2s  = (float*)(dsm + JSM_B2S);
    float* redm = (float*)(dsm + JSM_RM);
    float* reds = (float*)(dsm + JSM_RS);

    const int tid  = threadIdx.x;
    const int wid  = tid >> 5;
    const int lane = tid & 31;
    const int warp_m = wid & 3;
    const int warp_n = wid >> 2;
    const int lane4 = lane & 3;
    const int grp   = lane >> 2;

    const int pair = blockIdx.x >> 2;
    const int t0   = (blockIdx.x & 3) * 128;
    const int b    = pair / UU;

    if (tid < KK) b2s[tid] = b2[tid];

    const float* imgp = g_img_pre + (size_t)(b*TT + t0)*HH;
    const float* labp = g_lab_pre + (size_t)pair*HH;

    // staging role: row r (0..127), half hb (0 or 32 h-values)
    const int r  = tid >> 1;
    const int hb = (tid & 1) * 32;
    const uint32_t arel = (uint32_t)(r*128 + hb*2);  // bytes within a tile

    float acc[2][8][4];
    #pragma unroll
    for (int mi = 0; mi < 2; mi++)
        #pragma unroll
        for (int ni = 0; ni < 8; ni++)
            #pragma unroll
            for (int j = 0; j < 4; j++) acc[mi][ni][j] = 0.f;

    // -------- prologue: stage chunk 0 into buffer 0 --------
    {
        const char* wsrc = (const char*)(g_w2bf + (size_t)r*HH + hb);
        #pragma unroll
        for (int j = 0; j < 4; j++){
            uint32_t rel = arel + j*16;
            cp_async16(sb + JSM_B0 + (rel ^ ((rel >> 3) & 0x70)), wsrc + j*16);
        }
        cp_commit();
        const float* ia = imgp + (size_t)r*HH + hb;
        const float* la = labp + hb;
        #pragma unroll
        for (int j = 0; j < 4; j++){
            float4 i0 = *(const float4*)&ia[j*8];
            float4 i1 = *(const float4*)&ia[j*8+4];
            float4 l0 = *(const float4*)&la[j*8];
            float4 l1 = *(const float4*)&la[j*8+4];
            __nv_bfloat162 p0 = __floats2bfloat162_rn(tanh_hw(i0.x+l0.x), tanh_hw(i0.y+l0.y));
            __nv_bfloat162 p1 = __floats2bfloat162_rn(tanh_hw(i0.z+l0.z), tanh_hw(i0.w+l0.w));
            __nv_bfloat162 p2 = __floats2bfloat162_rn(tanh_hw(i1.x+l1.x), tanh_hw(i1.y+l1.y));
            __nv_bfloat162 p3 = __floats2bfloat162_rn(tanh_hw(i1.z+l1.z), tanh_hw(i1.w+l1.w));
            uint32_t rel = arel + j*16;
            uint32_t addr = sb + JSM_A0 + (rel ^ ((rel >> 3) & 0x70));
            asm volatile("st.shared.v4.b32 [%0], {%1,%2,%3,%4};"
                :: "r"(addr), "r"(*(uint32_t*)&p0), "r"(*(uint32_t*)&p1),
                   "r"(*(uint32_t*)&p2), "r"(*(uint32_t*)&p3));
        }
        cp_wait0();
    }
    __syncthreads();

    // -------- main pipelined loop: per-kstep interleaved A prefetch --------
    for (int c = 0; c < 16; c++){
        const int s  = c & 1;
        const int hn = c*64 + 64;
        const uint32_t Ab = sb + (s ? JSM_A1 : JSM_A0);
        const uint32_t Bb = sb + (s ? JSM_B1 : JSM_B0);
        const uint32_t An = sb + (s ? JSM_A0 : JSM_A1);
        const uint32_t Bn = sb + (s ? JSM_B0 : JSM_B1);

        if (c < 15){
            const char* wsrc = (const char*)(g_w2bf + (size_t)r*HH + hn + hb);
            #pragma unroll
            for (int j = 0; j < 4; j++){
                uint32_t rel = arel + j*16;
                cp_async16(Bn + (rel ^ ((rel >> 3) & 0x70)), wsrc + j*16);
            }
            cp_commit();
        }

        #pragma unroll
        for (int kk = 0; kk < 4; kk++){
            // prefetch this kstep's slice of A(c+1): 8 floats
            float4 p0, p1;
            if (c < 15){
                const float* ia = imgp + (size_t)r*HH + hn + hb + kk*8;
                p0 = *(const float4*)&ia[0];
                p1 = *(const float4*)&ia[4];
            }
            // MMA on buffer s, kstep kk
            const int colb = kk*32 + (lane >> 4)*16;
            uint32_t af[2][4];
            #pragma unroll
            for (int mi = 0; mi < 2; mi++)
                ldsm_x4(af[mi], sw_addr(Ab, warp_m*32 + mi*16 + (lane & 15), colb));
            uint32_t bf[4][4];
            #pragma unroll
            for (int p = 0; p < 4; p++)
                ldsm_x4(bf[p], sw_addr(Bb, warp_n*64 + p*16 + (lane & 15), colb));
            #pragma unroll
            for (int mi = 0; mi < 2; mi++)
                #pragma unroll
                for (int p = 0; p < 4; p++){
                    mma16816(acc[mi][2*p  ], af[mi], bf[p][0], bf[p][2]);
                    mma16816(acc[mi][2*p+1], af[mi], bf[p][1], bf[p][3]);
                }
            // finish this kstep's A(c+1) slice: tanh, cvt, store
            if (c < 15){
                const float* la = labp + hn + hb + kk*8;
                float4 l0 = *(const float4*)&la[0];
                float4 l1 = *(const float4*)&la[4];
                __nv_bfloat162 q0 = __floats2bfloat162_rn(tanh_hw(p0.x+l0.x), tanh_hw(p0.y+l0.y));
                __nv_bfloat162 q1 = __floats2bfloat162_rn(tanh_hw(p0.z+l0.z), tanh_hw(p0.w+l0.w));
                __nv_bfloat162 q2 = __floats2bfloat162_rn(tanh_hw(p1.x+l1.x), tanh_hw(p1.y+l1.y));
                __nv_bfloat162 q3 = __floats2bfloat162_rn(tanh_hw(p1.z+l1.z), tanh_hw(p1.w+l1.w));
                uint32_t rel = arel + kk*16;
                uint32_t addr = An + (rel ^ ((rel >> 3) & 0x70));
                asm volatile("st.shared.v4.b32 [%0], {%1,%2,%3,%4};"
                    :: "r"(addr), "r"(*(uint32_t*)&q0), "r"(*(uint32_t*)&q1),
                       "r"(*(uint32_t*)&q2), "r"(*(uint32_t*)&q3));
            }
        }
        if (c < 15) cp_wait0();
        __syncthreads();
    }

    // ---- epilogue: +b2, log_softmax over k (row split across 2 n-warps) ----
    #pragma unroll
    for (int ni = 0; ni < 8; ni++){
        float2 bv = *(const float2*)&b2s[warp_n*64 + ni*8 + 2*lane4];
        #pragma unroll
        for (int mi = 0; mi < 2; mi++){
            acc[mi][ni][0] += bv.x; acc[mi][ni][1] += bv.y;
            acc[mi][ni][2] += bv.x; acc[mi][ni][3] += bv.y;
        }
    }
    float rm[2][2];
    #pragma unroll
    for (int mi = 0; mi < 2; mi++)
        #pragma unroll
        for (int h = 0; h < 2; h++){
            float m = -1e30f;
            #pragma unroll
            for (int ni = 0; ni < 8; ni++)
                m = fmaxf(m, fmaxf(acc[mi][ni][2*h], acc[mi][ni][2*h+1]));
            #pragma unroll
            for (int d = 1; d < 4; d <<= 1)
                m = fmaxf(m, __shfl_xor_sync(0xffffffffu, m, d));
            rm[mi][h] = m;
        }
    if (lane4 == 0){
        #pragma unroll
        for (int mi = 0; mi < 2; mi++)
            #pragma unroll
            for (int h = 0; h < 2; h++)
                redm[warp_n*128 + warp_m*32 + mi*16 + grp + 8*h] = rm[mi][h];
    }
    __syncthreads();
    float mx[2][2], sm[2][2];
    #pragma unroll
    for (int mi = 0; mi < 2; mi++)
        #pragma unroll
        for (int h = 0; h < 2; h++){
            int row = warp_m*32 + mi*16 + grp + 8*h;
            mx[mi][h] = fmaxf(redm[row], redm[128 + row]);
            float s = 0.f;
            #pragma unroll
            for (int ni = 0; ni < 8; ni++)
                s += __expf(acc[mi][ni][2*h] - mx[mi][h]) + __expf(acc[mi][ni][2*h+1] - mx[mi][h]);
            #pragma unroll
            for (int d = 1; d < 4; d <<= 1)
                s += __shfl_xor_sync(0xffffffffu, s, d);
            sm[mi][h] = s;
        }
    if (lane4 == 0){
        #pragma unroll
        for (int mi = 0; mi < 2; mi++)
            #pragma unroll
            for (int h = 0; h < 2; h++)
                reds[warp_n*128 + warp_m*32 + mi*16 + grp + 8*h] = sm[mi][h];
    }
    __syncthreads();
    float* outj = out + SEG_ELEMS + (size_t)(pair*TT + t0)*KK;
    #pragma unroll
    for (int mi = 0; mi < 2; mi++)
        #pragma unroll
        for (int h = 0; h < 2; h++){
            int row = warp_m*32 + mi*16 + grp + 8*h;
            float L = mx[mi][h] + __logf(reds[row] + reds[128 + row]);
            float* orow = outj + row*KK + warp_n*64;
            #pragma unroll
            for (int ni = 0; ni < 8; ni++)
                *(float2*)&orow[ni*8 + 2*lane4] =
                    make_float2(acc[mi][ni][2*h] - L, acc[mi][ni][2*h+1] - L);
        }
}

// ---------------------------------------------------------------------------
extern "C" void kernel_launch(void* const* d_in, const int* in_sizes, int n_in,
                              void* d_out, int out_size)
{
    (void)in_sizes; (void)n_in; (void)out_size;
    const float* img   = (const float*)d_in[0];  // (B,T,D)
    const float* lab   = (const float*)d_in[1];  // (B,U,D)
    const float* masks = (const float*)d_in[2];  // (B,1,T)
    const float* W1    = (const float*)d_in[3];  // (H,2D)
    const float* b1    = (const float*)d_in[4];  // (H)
    const float* W2    = (const float*)d_in[5];  // (K,H)
    const float* b2    = (const float*)d_in[6];  // (K)
    const float* convw = (const float*)d_in[7];  // (K,D)
    const float* convb = (const float*)d_in[8];  // (K)
    float* out = (float*)d_out;

    cudaFuncSetAttribute(prep_tc_kernel,
                         cudaFuncAttributeMaxDynamicSharedMemorySize, PSM_TOTAL);
    cudaFuncSetAttribute(joint_mma_kernel,
                         cudaFuncAttributeMaxDynamicSharedMemorySize, JSM_TOTAL);

    prep_tc_kernel<<<88, 256, PSM_TOTAL>>>(img, lab, W1, b1, convw, convb, masks, W2, out);
    joint_mma_kernel<<<384, 256, JSM_TOTAL>>>(b2, out);
}

// round 13
// speedup vs baseline: 3.0814x; 1.1357x over previous
#include <cuda_runtime.h>
#include <cuda_bf16.h>
#include <cstdint>

// Problem constants
#define BB 2
#define TT 512
#define UU 48
#define DD 512
#define HH 1024
#define KK 128
#define SEG_ELEMS (BB*KK*TT)   // 131072 floats, first part of d_out

// Scratch (allocation-free rule: __device__ globals)
__device__ float g_img_pre[BB*TT*HH];           // [(b*T+t)][h] : img @ Wi^T (fp32)
__device__ float g_lab_pre[BB*UU*HH];           // [(b*U+u)][h] : lab @ Wl^T + b1 (fp32)
__device__ __nv_bfloat16 g_w2bf[KK*HH];         // W2 bf16, native (k,h) layout = B^T row-major

__device__ __forceinline__ float tanh_hw(float x){
    asm("tanh.approx.f32 %0, %0;" : "+f"(x)); return x;
}
__device__ __forceinline__ uint32_t smem_u32(const void* p){
    uint32_t a;
    asm("{ .reg .u64 t; cvta.to.shared.u64 t, %1; cvt.u32.u64 %0, t; }" : "=r"(a) : "l"(p));
    return a;
}
__device__ __forceinline__ void ldsm_x4(uint32_t* r, uint32_t addr){
    asm volatile("ldmatrix.sync.aligned.m8n8.x4.shared.b16 {%0,%1,%2,%3}, [%4];"
        : "=r"(r[0]), "=r"(r[1]), "=r"(r[2]), "=r"(r[3]) : "r"(addr));
}
__device__ __forceinline__ void mma16816(float* c, const uint32_t* a, uint32_t b0, uint32_t b1){
    asm volatile("mma.sync.aligned.m16n8k16.row.col.f32.bf16.bf16.f32 "
        "{%0,%1,%2,%3}, {%4,%5,%6,%7}, {%8,%9}, {%0,%1,%2,%3};"
        : "+f"(c[0]), "+f"(c[1]), "+f"(c[2]), "+f"(c[3])
        : "r"(a[0]), "r"(a[1]), "r"(a[2]), "r"(a[3]), "r"(b0), "r"(b1));
}
__device__ __forceinline__ void mma1688_tf32(float* c, const uint32_t* a, uint32_t b0, uint32_t b1){
    asm volatile("mma.sync.aligned.m16n8k8.row.col.f32.tf32.tf32.f32 "
        "{%0,%1,%2,%3}, {%4,%5,%6,%7}, {%8,%9}, {%0,%1,%2,%3};"
        : "+f"(c[0]), "+f"(c[1]), "+f"(c[2]), "+f"(c[3])
        : "r"(a[0]), "r"(a[1]), "r"(a[2]), "r"(a[3]), "r"(b0), "r"(b1));
}
__device__ __forceinline__ uint32_t sw_addr(uint32_t base, int row, int colb){
    uint32_t rel = (uint32_t)(row*128 + colb);
    return base + (rel ^ ((rel >> 3) & 0x70));
}
__device__ __forceinline__ void cp_async16(uint32_t dst, const void* src){
    asm volatile("cp.async.cg.shared.global [%0], [%1], 16;" :: "r"(dst), "l"(src));
}
__device__ __forceinline__ void cp_commit(){ asm volatile("cp.async.commit_group;" ::: "memory"); }
__device__ __forceinline__ void cp_wait0(){ asm volatile("cp.async.wait_group 0;" ::: "memory"); }
__device__ __forceinline__ uint32_t f2tf32(float x){
    uint32_t r; asm("cvt.rna.tf32.f32 %0, %1;" : "=r"(r) : "f"(x)); return r;
}
__device__ __forceinline__ float lds32(uint32_t addr){
    float v; asm volatile("ld.shared.f32 %0, [%1];" : "=f"(v) : "r"(addr)); return v;
}

// ---------------------------------------------------------------------------
// Prep kernel, tf32 tensor-core: 3 NT-GEMMs + W2 bf16 convert. 88 CTAs.
// (unchanged from R12 — measured good)
// ---------------------------------------------------------------------------
#define PSM_A0 0u
#define PSM_A1 16384u
#define PSM_B0 32768u
#define PSM_B1 49152u
#define PSM_TOTAL 65536

__global__ __launch_bounds__(256, 2) void prep_tc_kernel(
    const float* __restrict__ img, const float* __restrict__ lab,
    const float* __restrict__ W1, const float* __restrict__ b1,
    const float* __restrict__ convw, const float* __restrict__ convb,
    const float* __restrict__ masks, const float* __restrict__ W2,
    float* __restrict__ out)
{
    extern __shared__ char dsm[];
    const int bx  = blockIdx.x;
    const int tid = threadIdx.x;

    if (bx >= 80){
        int base = (bx - 80)*16384 + tid*4;
        #pragma unroll
        for (int q = 0; q < 16; q++){
            int i = base + q*1024;
            float4 wv = *(const float4*)&W2[i];
            __nv_bfloat162 p0 = __floats2bfloat162_rn(wv.x, wv.y);
            __nv_bfloat162 p1 = __floats2bfloat162_rn(wv.z, wv.w);
            uint2 u; u.x = *(uint32_t*)&p0; u.y = *(uint32_t*)&p1;
            *(uint2*)&g_w2bf[i] = u;
        }
        return;
    }

    const uint32_t sb = smem_u32(dsm);
    const float* A; const float* Bp;
    int ldb, M, m0, n0, job;
    if (bx < 64)      { job=0; A=img; Bp=W1+DD; ldb=2*DD; M=BB*TT; m0=(bx&7)*128;  n0=(bx>>3)*128; }
    else if (bx < 72) { job=1; A=lab; Bp=W1;    ldb=2*DD; M=BB*UU; m0=0;           n0=(bx-64)*128; }
    else              { job=2; A=img; Bp=convw; ldb=DD;   M=BB*TT; m0=(bx-72)*128; n0=0; }

    const int wid  = tid >> 5;
    const int lane = tid & 31;
    const int warp_m = wid & 3;
    const int warp_n = wid >> 2;
    const int lane4 = lane & 3;
    const int grp   = lane >> 2;

    const int r    = tid >> 1;
    const int cb0  = (tid & 1) * 16;
    const bool avalid = (m0 + r) < M;
    const float* arow = A  + (size_t)(m0 + r)*DD;
    const float* brow = Bp + (size_t)(n0 + r)*ldb;

    float acc[2][8][4];
    #pragma unroll
    for (int mi = 0; mi < 2; mi++)
        #pragma unroll
        for (int ni = 0; ni < 8; ni++)
            #pragma unroll
            for (int j = 0; j < 4; j++) acc[mi][ni][j] = 0.f;

    #pragma unroll
    for (int kk = 0; kk < 4; kk++){
        int col = cb0 + kk*4;
        float4 av = avalid ? *(const float4*)&arow[col] : make_float4(0,0,0,0);
        float4 bv = *(const float4*)&brow[col];
        uint4 at, bt;
        at.x = f2tf32(av.x); at.y = f2tf32(av.y); at.z = f2tf32(av.z); at.w = f2tf32(av.w);
        bt.x = f2tf32(bv.x); bt.y = f2tf32(bv.y); bt.z = f2tf32(bv.z); bt.w = f2tf32(bv.w);
        uint32_t aa = sw_addr(sb + PSM_A0, r, col*4);
        uint32_t ba = sw_addr(sb + PSM_B0, r, col*4);
        asm volatile("st.shared.v4.b32 [%0], {%1,%2,%3,%4};"
            :: "r"(aa), "r"(at.x), "r"(at.y), "r"(at.z), "r"(at.w));
        asm volatile("st.shared.v4.b32 [%0], {%1,%2,%3,%4};"
            :: "r"(ba), "r"(bt.x), "r"(bt.y), "r"(bt.z), "r"(bt.w));
    }
    __syncthreads();

    for (int c = 0; c < 16; c++){
        const int s  = c & 1;
        const int dn = c*32 + 32;
        const uint32_t Ab = sb + (s ? PSM_A1 : PSM_A0);
        const uint32_t Bb = sb + (s ? PSM_B1 : PSM_B0);
        const uint32_t An = sb + (s ? PSM_A0 : PSM_A1);
        const uint32_t Bn = sb + (s ? PSM_B0 : PSM_B1);

        #pragma unroll
        for (int kk = 0; kk < 4; kk++){
            float4 av, bv;
            if (c < 15){
                int col = dn + cb0 + kk*4;
                av = avalid ? *(const float4*)&arow[col] : make_float4(0,0,0,0);
                bv = *(const float4*)&brow[col];
            }
            const int ca = (kk*8 + lane4)*4;
            const int cc = (kk*8 + lane4 + 4)*4;
            uint32_t af[2][4];
            #pragma unroll
            for (int mi = 0; mi < 2; mi++){
                int rb = warp_m*32 + mi*16;
                af[mi][0] = __float_as_uint(lds32(sw_addr(Ab, rb + grp,     ca)));
                af[mi][1] = __float_as_uint(lds32(sw_addr(Ab, rb + grp + 8, ca)));
                af[mi][2] = __float_as_uint(lds32(sw_addr(Ab, rb + grp,     cc)));
                af[mi][3] = __float_as_uint(lds32(sw_addr(Ab, rb + grp + 8, cc)));
            }
            #pragma unroll
            for (int ni = 0; ni < 8; ni++){
                int rn = warp_n*64 + ni*8 + grp;
                uint32_t b0 = __float_as_uint(lds32(sw_addr(Bb, rn, ca)));
                uint32_t b1 = __float_as_uint(lds32(sw_addr(Bb, rn, cc)));
                mma1688_tf32(acc[0][ni], af[0], b0, b1);
                mma1688_tf32(acc[1][ni], af[1], b0, b1);
            }
            if (c < 15){
                int col = cb0 + kk*4;
                uint4 at, bt;
                at.x = f2tf32(av.x); at.y = f2tf32(av.y); at.z = f2tf32(av.z); at.w = f2tf32(av.w);
                bt.x = f2tf32(bv.x); bt.y = f2tf32(bv.y); bt.z = f2tf32(bv.z); bt.w = f2tf32(bv.w);
                asm volatile("st.shared.v4.b32 [%0], {%1,%2,%3,%4};"
                    :: "r"(sw_addr(An, r, col*4)), "r"(at.x), "r"(at.y), "r"(at.z), "r"(at.w));
                asm volatile("st.shared.v4.b32 [%0], {%1,%2,%3,%4};"
                    :: "r"(sw_addr(Bn, r, col*4)), "r"(bt.x), "r"(bt.y), "r"(bt.z), "r"(bt.w));
            }
        }
        __syncthreads();
    }

    if (job == 0){
        #pragma unroll
        for (int mi = 0; mi < 2; mi++)
            #pragma unroll
            for (int h = 0; h < 2; h++){
                int m = m0 + warp_m*32 + mi*16 + grp + 8*h;
                float* orow = g_img_pre + (size_t)m*HH + n0 + warp_n*64;
                #pragma unroll
                for (int ni = 0; ni < 8; ni++)
                    *(float2*)&orow[ni*8 + 2*lane4] =
                        make_float2(acc[mi][ni][2*h], acc[mi][ni][2*h+1]);
            }
    } else if (job == 1){
        #pragma unroll
        for (int mi = 0; mi < 2; mi++)
            #pragma unroll
            for (int h = 0; h < 2; h++){
                int m = warp_m*32 + mi*16 + grp + 8*h;
                if (m < BB*UU){
                    float* orow = g_lab_pre + (size_t)m*HH + n0 + warp_n*64;
                    #pragma unroll
                    for (int ni = 0; ni < 8; ni++){
                        int n = ni*8 + 2*lane4;
                        float2 bb = *(const float2*)&b1[n0 + warp_n*64 + n];
                        *(float2*)&orow[n] =
                            make_float2(acc[mi][ni][2*h] + bb.x, acc[mi][ni][2*h+1] + bb.y);
                    }
                }
            }
    } else {
        #pragma unroll
        for (int mi = 0; mi < 2; mi++)
            #pragma unroll
            for (int h = 0; h < 2; h++){
                int m = m0 + warp_m*32 + mi*16 + grp + 8*h;
                float mk = masks[m];
                int b = m >> 9, t = m & 511;
                #pragma unroll
                for (int ni = 0; ni < 8; ni++){
                    int n = warp_n*64 + ni*8 + 2*lane4;
                    float2 cbv = *(const float2*)&convb[n];
                    out[(b*KK + n  )*TT + t] = (acc[mi][ni][2*h  ] + cbv.x)*mk;
                    out[(b*KK + n+1)*TT + t] = (acc[mi][ni][2*h+1] + cbv.y)*mk;
                }
            }
    }
}

// ---------------------------------------------------------------------------
// Joint kernel: 64(t) x 128(k) tile, occ 3 (85-reg cap), bf16 HMMA.
// 768 CTAs (96 pairs x 8 t-tiles); 8 warps = 4(m:16 rows) x 2(n:64 cols),
// 32 accs/thread. Double-buffered; A prefetch split in two 8-float halves
// interleaved between kstep pairs (<=8 extra live regs).
// ---------------------------------------------------------------------------
#define JSM_A0   0u
#define JSM_A1   8192u
#define JSM_B0   16384u
#define JSM_B1   32768u
#define JSM_B2S  49152u
#define JSM_RM   49664u   // 2*64 floats
#define JSM_RS   50176u
#define JSM_TOTAL 50688

__global__ __launch_bounds__(256, 3)
void joint_mma_kernel(const float* __restrict__ b2, float* __restrict__ out)
{
    extern __shared__ char dsm[];
    const uint32_t sb = smem_u32(dsm);
    float* b2s  = (float*)(dsm + JSM_B2S);
    float* redm = (float*)(dsm + JSM_RM);
    float* reds = (float*)(dsm + JSM_RS);

    const int tid  = threadIdx.x;
    const int wid  = tid >> 5;
    const int lane = tid & 31;
    const int warp_m = wid & 3;     // 16 t-rows each
    const int warp_n = wid >> 2;    // 64 k-cols each
    const int lane4 = lane & 3;
    const int grp   = lane >> 2;

    const int pair = blockIdx.x >> 3;        // b*U+u
    const int t0   = (blockIdx.x & 7) * 64;
    const int b    = pair / UU;

    if (tid < KK) b2s[tid] = b2[tid];

    const float* imgp = g_img_pre + (size_t)(b*TT + t0)*HH;
    const float* labp = g_lab_pre + (size_t)pair*HH;

    // A staging role: row ra (0..63), 16 h-values at qa
    const int ra = tid >> 2;
    const int qa = (tid & 3) * 16;
    const uint32_t arel = (uint32_t)(ra*128 + qa*2);
    // B staging role: row rb (0..127), 32 h-values at hbB
    const int rb = tid >> 1;
    const int hbB = (tid & 1) * 32;
    const uint32_t brel = (uint32_t)(rb*128 + hbB*2);

    float acc[8][4];
    #pragma unroll
    for (int ni = 0; ni < 8; ni++)
        #pragma unroll
        for (int j = 0; j < 4; j++) acc[ni][j] = 0.f;

    // -------- prologue: stage chunk 0 into buffer 0 --------
    {
        const char* wsrc = (const char*)(g_w2bf + (size_t)rb*HH + hbB);
        #pragma unroll
        for (int j = 0; j < 4; j++){
            uint32_t rel = brel + j*16;
            cp_async16(sb + JSM_B0 + (rel ^ ((rel >> 3) & 0x70)), wsrc + j*16);
        }
        cp_commit();
        const float* ia = imgp + (size_t)ra*HH + qa;
        const float* la = labp + qa;
        #pragma unroll
        for (int j = 0; j < 2; j++){
            float4 i0 = *(const float4*)&ia[j*8];
            float4 i1 = *(const float4*)&ia[j*8+4];
            float4 l0 = *(const float4*)&la[j*8];
            float4 l1 = *(const float4*)&la[j*8+4];
            __nv_bfloat162 p0 = __floats2bfloat162_rn(tanh_hw(i0.x+l0.x), tanh_hw(i0.y+l0.y));
            __nv_bfloat162 p1 = __floats2bfloat162_rn(tanh_hw(i0.z+l0.z), tanh_hw(i0.w+l0.w));
            __nv_bfloat162 p2 = __floats2bfloat162_rn(tanh_hw(i1.x+l1.x), tanh_hw(i1.y+l1.y));
            __nv_bfloat162 p3 = __floats2bfloat162_rn(tanh_hw(i1.z+l1.z), tanh_hw(i1.w+l1.w));
            uint32_t rel = arel + j*16;
            uint32_t addr = sb + JSM_A0 + (rel ^ ((rel >> 3) & 0x70));
            asm volatile("st.shared.v4.b32 [%0], {%1,%2,%3,%4};"
                :: "r"(addr), "r"(*(uint32_t*)&p0), "r"(*(uint32_t*)&p1),
                   "r"(*(uint32_t*)&p2), "r"(*(uint32_t*)&p3));
        }
        cp_wait0();
    }
    __syncthreads();

    // -------- main loop --------
    for (int c = 0; c < 16; c++){
        const int s  = c & 1;
        const int hn = c*64 + 64;
        const uint32_t Ab = sb + (s ? JSM_A1 : JSM_A0);
        const uint32_t Bb = sb + (s ? JSM_B1 : JSM_B0);
        const uint32_t An = sb + (s ? JSM_A0 : JSM_A1);
        const uint32_t Bn = sb + (s ? JSM_B0 : JSM_B1);

        if (c < 15){
            const char* wsrc = (const char*)(g_w2bf + (size_t)rb*HH + hn + hbB);
            #pragma unroll
            for (int j = 0; j < 4; j++){
                uint32_t rel = brel + j*16;
                cp_async16(Bn + (rel ^ ((rel >> 3) & 0x70)), wsrc + j*16);
            }
            cp_commit();
        }

        // first half of A(c+1) prefetch
        float4 p0, p1;
        if (c < 15){
            const float* ia = imgp + (size_t)ra*HH + hn + qa;
            p0 = *(const float4*)&ia[0];
            p1 = *(const float4*)&ia[4];
        }

        #pragma unroll
        for (int half = 0; half < 2; half++){
            #pragma unroll
            for (int k2 = 0; k2 < 2; k2++){
                const int kk = half*2 + k2;
                const int colb = kk*32 + (lane >> 4)*16;
                uint32_t af[4];
                ldsm_x4(af, sw_addr(Ab, warp_m*16 + (lane & 15), colb));
                uint32_t bf[4][4];
                #pragma unroll
                for (int p = 0; p < 4; p++)
                    ldsm_x4(bf[p], sw_addr(Bb, warp_n*64 + p*16 + (lane & 15), colb));
                #pragma unroll
                for (int p = 0; p < 4; p++){
                    mma16816(acc[2*p  ], af, bf[p][0], bf[p][2]);
                    mma16816(acc[2*p+1], af, bf[p][1], bf[p][3]);
                }
            }
            // after each kstep pair: finish this half of A(c+1), start next half
            if (c < 15){
                const float* la = labp + hn + qa + half*8;
                float4 l0 = *(const float4*)&la[0];
                float4 l1 = *(const float4*)&la[4];
                __nv_bfloat162 q0 = __floats2bfloat162_rn(tanh_hw(p0.x+l0.x), tanh_hw(p0.y+l0.y));
                __nv_bfloat162 q1 = __floats2bfloat162_rn(tanh_hw(p0.z+l0.z), tanh_hw(p0.w+l0.w));
                __nv_bfloat162 q2 = __floats2bfloat162_rn(tanh_hw(p1.x+l1.x), tanh_hw(p1.y+l1.y));
                __nv_bfloat162 q3 = __floats2bfloat162_rn(tanh_hw(p1.z+l1.z), tanh_hw(p1.w+l1.w));
                uint32_t rel = arel + half*16;
                uint32_t addr = An + (rel ^ ((rel >> 3) & 0x70));
                asm volatile("st.shared.v4.b32 [%0], {%1,%2,%3,%4};"
                    :: "r"(addr), "r"(*(uint32_t*)&q0), "r"(*(uint32_t*)&q1),
                       "r"(*(uint32_t*)&q2), "r"(*(uint32_t*)&q3));
                if (half == 0){
                    const float* ia = imgp + (size_t)ra*HH + hn + qa + 8;
                    p0 = *(const float4*)&ia[0];
                    p1 = *(const float4*)&ia[4];
                }
            }
        }
        if (c < 15) cp_wait0();
        __syncthreads();
    }

    // ---- epilogue: +b2, log_softmax over k (row split across 2 n-warps) ----
    #pragma unroll
    for (int ni = 0; ni < 8; ni++){
        float2 bv = *(const float2*)&b2s[warp_n*64 + ni*8 + 2*lane4];
        acc[ni][0] += bv.x; acc[ni][1] += bv.y;
        acc[ni][2] += bv.x; acc[ni][3] += bv.y;
    }
    float rm[2];
    #pragma unroll
    for (int h = 0; h < 2; h++){
        float m = -1e30f;
        #pragma unroll
        for (int ni = 0; ni < 8; ni++)
            m = fmaxf(m, fmaxf(acc[ni][2*h], acc[ni][2*h+1]));
        #pragma unroll
        for (int d = 1; d < 4; d <<= 1)
            m = fmaxf(m, __shfl_xor_sync(0xffffffffu, m, d));
        rm[h] = m;
    }
    if (lane4 == 0){
        #pragma unroll
        for (int h = 0; h < 2; h++)
            redm[warp_n*64 + warp_m*16 + grp + 8*h] = rm[h];
    }
    __syncthreads();
    float mx[2], sm[2];
    #pragma unroll
    for (int h = 0; h < 2; h++){
        int row = warp_m*16 + grp + 8*h;
        mx[h] = fmaxf(redm[row], redm[64 + row]);
        float s = 0.f;
        #pragma unroll
        for (int ni = 0; ni < 8; ni++)
            s += __expf(acc[ni][2*h] - mx[h]) + __expf(acc[ni][2*h+1] - mx[h]);
        #pragma unroll
        for (int d = 1; d < 4; d <<= 1)
            s += __shfl_xor_sync(0xffffffffu, s, d);
        sm[h] = s;
    }
    if (lane4 == 0){
        #pragma unroll
        for (int h = 0; h < 2; h++)
            reds[warp_n*64 + warp_m*16 + grp + 8*h] = sm[h];
    }
    __syncthreads();
    float* outj = out + SEG_ELEMS + (size_t)(pair*TT + t0)*KK;
    #pragma unroll
    for (int h = 0; h < 2; h++){
        int row = warp_m*16 + grp + 8*h;
        float L = mx[h] + __logf(reds[row] + reds[64 + row]);
        float* orow = outj + row*KK + warp_n*64;
        #pragma unroll
        for (int ni = 0; ni < 8; ni++)
            *(float2*)&orow[ni*8 + 2*lane4] =
                make_float2(acc[ni][2*h] - L, acc[ni][2*h+1] - L);
    }
}

// ---------------------------------------------------------------------------
extern "C" void kernel_launch(void* const* d_in, const int* in_sizes, int n_in,
                              void* d_out, int out_size)
{
    (void)in_sizes; (void)n_in; (void)out_size;
    const float* img   = (const float*)d_in[0];  // (B,T,D)
    const float* lab   = (const float*)d_in[1];  // (B,U,D)
    const float* masks = (const float*)d_in[2];  // (B,1,T)
    const float* W1    = (const float*)d_in[3];  // (H,2D)
    const float* b1    = (const float*)d_in[4];  // (H)
    const float* W2    = (const float*)d_in[5];  // (K,H)
    const float* b2    = (const float*)d_in[6];  // (K)
    const float* convw = (const float*)d_in[7];  // (K,D)
    const float* convb = (const float*)d_in[8];  // (K)
    float* out = (float*)d_out;

    cudaFuncSetAttribute(prep_tc_kernel,
                         cudaFuncAttributeMaxDynamicSharedMemorySize, PSM_TOTAL);
    cudaFuncSetAttribute(joint_mma_kernel,
                         cudaFuncAttributeMaxDynamicSharedMemorySize, JSM_TOTAL);

    prep_tc_kernel<<<88, 256, PSM_TOTAL>>>(img, lab, W1, b1, convw, convb, masks, W2, out);
    joint_mma_kernel<<<768, 256, JSM_TOTAL>>>(b2, out);
}

// round 14
// speedup vs baseline: 3.0878x; 1.0021x over previous
#include <cuda_runtime.h>
#include <cuda_bf16.h>
#include <cstdint>

// Problem constants
#define BB 2
#define TT 512
#define UU 48
#define DD 512
#define HH 1024
#define KK 128
#define SEG_ELEMS (BB*KK*TT)   // 131072 floats, first part of d_out

// Scratch (allocation-free rule: __device__ globals)
__device__ float g_img_pre[BB*TT*HH];           // [(b*T+t)][h] : img @ Wi^T (fp32)
__device__ float g_lab_pre[BB*UU*HH];           // [(b*U+u)][h] : lab @ Wl^T + b1 (fp32)
__device__ __nv_bfloat16 g_w2bf[KK*HH];         // W2 bf16, native (k,h) layout = B^T row-major

__device__ __forceinline__ float tanh_hw(float x){
    asm("tanh.approx.f32 %0, %0;" : "+f"(x)); return x;
}
__device__ __forceinline__ uint32_t smem_u32(const void* p){
    uint32_t a;
    asm("{ .reg .u64 t; cvta.to.shared.u64 t, %1; cvt.u32.u64 %0, t; }" : "=r"(a) : "l"(p));
    return a;
}
__device__ __forceinline__ void ldsm_x4(uint32_t* r, uint32_t addr){
    asm volatile("ldmatrix.sync.aligned.m8n8.x4.shared.b16 {%0,%1,%2,%3}, [%4];"
        : "=r"(r[0]), "=r"(r[1]), "=r"(r[2]), "=r"(r[3]) : "r"(addr));
}
__device__ __forceinline__ void mma16816(float* c, const uint32_t* a, uint32_t b0, uint32_t b1){
    asm volatile("mma.sync.aligned.m16n8k16.row.col.f32.bf16.bf16.f32 "
        "{%0,%1,%2,%3}, {%4,%5,%6,%7}, {%8,%9}, {%0,%1,%2,%3};"
        : "+f"(c[0]), "+f"(c[1]), "+f"(c[2]), "+f"(c[3])
        : "r"(a[0]), "r"(a[1]), "r"(a[2]), "r"(a[3]), "r"(b0), "r"(b1));
}
__device__ __forceinline__ void mma1688_tf32(float* c, const uint32_t* a, uint32_t b0, uint32_t b1){
    asm volatile("mma.sync.aligned.m16n8k8.row.col.f32.tf32.tf32.f32 "
        "{%0,%1,%2,%3}, {%4,%5,%6,%7}, {%8,%9}, {%0,%1,%2,%3};"
        : "+f"(c[0]), "+f"(c[1]), "+f"(c[2]), "+f"(c[3])
        : "r"(a[0]), "r"(a[1]), "r"(a[2]), "r"(a[3]), "r"(b0), "r"(b1));
}
__device__ __forceinline__ uint32_t sw_addr(uint32_t base, int row, int colb){
    uint32_t rel = (uint32_t)(row*128 + colb);
    return base + (rel ^ ((rel >> 3) & 0x70));
}
__device__ __forceinline__ void cp_async16(uint32_t dst, const void* src){
    asm volatile("cp.async.cg.shared.global [%0], [%1], 16;" :: "r"(dst), "l"(src));
}
__device__ __forceinline__ void cp_commit(){ asm volatile("cp.async.commit_group;" ::: "memory"); }
__device__ __forceinline__ void cp_wait0(){ asm volatile("cp.async.wait_group 0;" ::: "memory"); }
__device__ __forceinline__ uint32_t f2tf32(float x){
    uint32_t r; asm("cvt.rna.tf32.f32 %0, %1;" : "=r"(r) : "f"(x)); return r;
}
__device__ __forceinline__ float lds32(uint32_t addr){
    float v; asm volatile("ld.shared.f32 %0, [%1];" : "=f"(v) : "r"(addr)); return v;
}

// ---------------------------------------------------------------------------
// Prep kernel, tf32 tensor-core: 3 NT-GEMMs + W2 bf16 convert. 88 CTAs.
// (unchanged from R12 — measured good)
// ---------------------------------------------------------------------------
#define PSM_A0 0u
#define PSM_A1 16384u
#define PSM_B0 32768u
#define PSM_B1 49152u
#define PSM_TOTAL 65536

__global__ __launch_bounds__(256, 2) void prep_tc_kernel(
    const float* __restrict__ img, const float* __restrict__ lab,
    const float* __restrict__ W1, const float* __restrict__ b1,
    const float* __restrict__ convw, const float* __restrict__ convb,
    const float* __restrict__ masks, const float* __restrict__ W2,
    float* __restrict__ out)
{
    extern __shared__ char dsm[];
    const int bx  = blockIdx.x;
    const int tid = threadIdx.x;

    if (bx >= 80){
        int base = (bx - 80)*16384 + tid*4;
        #pragma unroll
        for (int q = 0; q < 16; q++){
            int i = base + q*1024;
            float4 wv = *(const float4*)&W2[i];
            __nv_bfloat162 p0 = __floats2bfloat162_rn(wv.x, wv.y);
            __nv_bfloat162 p1 = __floats2bfloat162_rn(wv.z, wv.w);
            uint2 u; u.x = *(uint32_t*)&p0; u.y = *(uint32_t*)&p1;
            *(uint2*)&g_w2bf[i] = u;
        }
        return;
    }

    const uint32_t sb = smem_u32(dsm);
    const float* A; const float* Bp;
    int ldb, M, m0, n0, job;
    if (bx < 64)      { job=0; A=img; Bp=W1+DD; ldb=2*DD; M=BB*TT; m0=(bx&7)*128;  n0=(bx>>3)*128; }
    else if (bx < 72) { job=1; A=lab; Bp=W1;    ldb=2*DD; M=BB*UU; m0=0;           n0=(bx-64)*128; }
    else              { job=2; A=img; Bp=convw; ldb=DD;   M=BB*TT; m0=(bx-72)*128; n0=0; }

    const int wid  = tid >> 5;
    const int lane = tid & 31;
    const int warp_m = wid & 3;
    const int warp_n = wid >> 2;
    const int lane4 = lane & 3;
    const int grp   = lane >> 2;

    const int r    = tid >> 1;
    const int cb0  = (tid & 1) * 16;
    const bool avalid = (m0 + r) < M;
    const float* arow = A  + (size_t)(m0 + r)*DD;
    const float* brow = Bp + (size_t)(n0 + r)*ldb;

    float acc[2][8][4];
    #pragma unroll
    for (int mi = 0; mi < 2; mi++)
        #pragma unroll
        for (int ni = 0; ni < 8; ni++)
            #pragma unroll
            for (int j = 0; j < 4; j++) acc[mi][ni][j] = 0.f;

    #pragma unroll
    for (int kk = 0; kk < 4; kk++){
        int col = cb0 + kk*4;
        float4 av = avalid ? *(const float4*)&arow[col] : make_float4(0,0,0,0);
        float4 bv = *(const float4*)&brow[col];
        uint4 at, bt;
        at.x = f2tf32(av.x); at.y = f2tf32(av.y); at.z = f2tf32(av.z); at.w = f2tf32(av.w);
        bt.x = f2tf32(bv.x); bt.y = f2tf32(bv.y); bt.z = f2tf32(bv.z); bt.w = f2tf32(bv.w);
        uint32_t aa = sw_addr(sb + PSM_A0, r, col*4);
        uint32_t ba = sw_addr(sb + PSM_B0, r, col*4);
        asm volatile("st.shared.v4.b32 [%0], {%1,%2,%3,%4};"
            :: "r"(aa), "r"(at.x), "r"(at.y), "r"(at.z), "r"(at.w));
        asm volatile("st.shared.v4.b32 [%0], {%1,%2,%3,%4};"
            :: "r"(ba), "r"(bt.x), "r"(bt.y), "r"(bt.z), "r"(bt.w));
    }
    __syncthreads();

    for (int c = 0; c < 16; c++){
        const int s  = c & 1;
        const int dn = c*32 + 32;
        const uint32_t Ab = sb + (s ? PSM_A1 : PSM_A0);
        const uint32_t Bb = sb + (s ? PSM_B1 : PSM_B0);
        const uint32_t An = sb + (s ? PSM_A0 : PSM_A1);
        const uint32_t Bn = sb + (s ? PSM_B0 : PSM_B1);

        #pragma unroll
        for (int kk = 0; kk < 4; kk++){
            float4 av, bv;
            if (c < 15){
                int col = dn + cb0 + kk*4;
                av = avalid ? *(const float4*)&arow[col] : make_float4(0,0,0,0);
                bv = *(const float4*)&brow[col];
            }
            const int ca = (kk*8 + lane4)*4;
            const int cc = (kk*8 + lane4 + 4)*4;
            uint32_t af[2][4];
            #pragma unroll
            for (int mi = 0; mi < 2; mi++){
                int rb = warp_m*32 + mi*16;
                af[mi][0] = __float_as_uint(lds32(sw_addr(Ab, rb + grp,     ca)));
                af[mi][1] = __float_as_uint(lds32(sw_addr(Ab, rb + grp + 8, ca)));
                af[mi][2] = __float_as_uint(lds32(sw_addr(Ab, rb + grp,     cc)));
                af[mi][3] = __float_as_uint(lds32(sw_addr(Ab, rb + grp + 8, cc)));
            }
            #pragma unroll
            for (int ni = 0; ni < 8; ni++){
                int rn = warp_n*64 + ni*8 + grp;
                uint32_t b0 = __float_as_uint(lds32(sw_addr(Bb, rn, ca)));
                uint32_t b1 = __float_as_uint(lds32(sw_addr(Bb, rn, cc)));
                mma1688_tf32(acc[0][ni], af[0], b0, b1);
                mma1688_tf32(acc[1][ni], af[1], b0, b1);
            }
            if (c < 15){
                int col = cb0 + kk*4;
                uint4 at, bt;
                at.x = f2tf32(av.x); at.y = f2tf32(av.y); at.z = f2tf32(av.z); at.w = f2tf32(av.w);
                bt.x = f2tf32(bv.x); bt.y = f2tf32(bv.y); bt.z = f2tf32(bv.z); bt.w = f2tf32(bv.w);
                asm volatile("st.shared.v4.b32 [%0], {%1,%2,%3,%4};"
                    :: "r"(sw_addr(An, r, col*4)), "r"(at.x), "r"(at.y), "r"(at.z), "r"(at.w));
                asm volatile("st.shared.v4.b32 [%0], {%1,%2,%3,%4};"
                    :: "r"(sw_addr(Bn, r, col*4)), "r"(bt.x), "r"(bt.y), "r"(bt.z), "r"(bt.w));
            }
        }
        __syncthreads();
    }

    if (job == 0){
        #pragma unroll
        for (int mi = 0; mi < 2; mi++)
            #pragma unroll
            for (int h = 0; h < 2; h++){
                int m = m0 + warp_m*32 + mi*16 + grp + 8*h;
                float* orow = g_img_pre + (size_t)m*HH + n0 + warp_n*64;
                #pragma unroll
                for (int ni = 0; ni < 8; ni++)
                    *(float2*)&orow[ni*8 + 2*lane4] =
                        make_float2(acc[mi][ni][2*h], acc[mi][ni][2*h+1]);
            }
    } else if (job == 1){
        #pragma unroll
        for (int mi = 0; mi < 2; mi++)
            #pragma unroll
            for (int h = 0; h < 2; h++){
                int m = warp_m*32 + mi*16 + grp + 8*h;
                if (m < BB*UU){
                    float* orow = g_lab_pre + (size_t)m*HH + n0 + warp_n*64;
                    #pragma unroll
                    for (int ni = 0; ni < 8; ni++){
                        int n = ni*8 + 2*lane4;
                        float2 bb = *(const float2*)&b1[n0 + warp_n*64 + n];
                        *(float2*)&orow[n] =
                            make_float2(acc[mi][ni][2*h] + bb.x, acc[mi][ni][2*h+1] + bb.y);
                    }
                }
            }
    } else {
        #pragma unroll
        for (int mi = 0; mi < 2; mi++)
            #pragma unroll
            for (int h = 0; h < 2; h++){
                int m = m0 + warp_m*32 + mi*16 + grp + 8*h;
                float mk = masks[m];
                int b = m >> 9, t = m & 511;
                #pragma unroll
                for (int ni = 0; ni < 8; ni++){
                    int n = warp_n*64 + ni*8 + 2*lane4;
                    float2 cbv = *(const float2*)&convb[n];
                    out[(b*KK + n  )*TT + t] = (acc[mi][ni][2*h  ] + cbv.x)*mk;
                    out[(b*KK + n+1)*TT + t] = (acc[mi][ni][2*h+1] + cbv.y)*mk;
                }
            }
    }
}

// ---------------------------------------------------------------------------
// Joint kernel: 64(t) x 128(k) tile, occ 3 (85-reg cap), bf16 HMMA.
// 768 CTAs (96 pairs x 8 t-tiles); 8 warps = 4(m:16 rows) x 2(n:64 cols),
// 32 accs/thread. Double-buffered; A prefetch split in two 8-float halves
// interleaved between kstep pairs (<=8 extra live regs).
// ---------------------------------------------------------------------------
#define JSM_A0   0u
#define JSM_A1   8192u
#define JSM_B0   16384u
#define JSM_B1   32768u
#define JSM_B2S  49152u
#define JSM_RM   49664u   // 2*64 floats
#define JSM_RS   50176u
#define JSM_TOTAL 50688

__global__ __launch_bounds__(256, 3)
void joint_mma_kernel(const float* __restrict__ b2, float* __restrict__ out)
{
    extern __shared__ char dsm[];
    const uint32_t sb = smem_u32(dsm);
    float* b2s  = (float*)(dsm + JSM_B2S);
    float* redm = (float*)(dsm + JSM_RM);
    float* reds = (float*)(dsm + JSM_RS);

    const int tid  = threadIdx.x;
    const int wid  = tid >> 5;
    const int lane = tid & 31;
    const int warp_m = wid & 3;     // 16 t-rows each
    const int warp_n = wid >> 2;    // 64 k-cols each
    const int lane4 = lane & 3;
    const int grp   = lane >> 2;

    const int pair = blockIdx.x >> 3;        // b*U+u
    const int t0   = (blockIdx.x & 7) * 64;
    const int b    = pair / UU;

    if (tid < KK) b2s[tid] = b2[tid];

    const float* imgp = g_img_pre + (size_t)(b*TT + t0)*HH;
    const float* labp = g_lab_pre + (size_t)pair*HH;

    // A staging role: row ra (0..63), 16 h-values at qa
    const int ra = tid >> 2;
    const int qa = (tid & 3) * 16;
    const uint32_t arel = (uint32_t)(ra*128 + qa*2);
    // B staging role: row rb (0..127), 32 h-values at hbB
    const int rb = tid >> 1;
    const int hbB = (tid & 1) * 32;
    const uint32_t brel = (uint32_t)(rb*128 + hbB*2);

    float acc[8][4];
    #pragma unroll
    for (int ni = 0; ni < 8; ni++)
        #pragma unroll
        for (int j = 0; j < 4; j++) acc[ni][j] = 0.f;

    // -------- prologue: stage chunk 0 into buffer 0 --------
    {
        const char* wsrc = (const char*)(g_w2bf + (size_t)rb*HH + hbB);
        #pragma unroll
        for (int j = 0; j < 4; j++){
            uint32_t rel = brel + j*16;
            cp_async16(sb + JSM_B0 + (rel ^ ((rel >> 3) & 0x70)), wsrc + j*16);
        }
        cp_commit();
        const float* ia = imgp + (size_t)ra*HH + qa;
        const float* la = labp + qa;
        #pragma unroll
        for (int j = 0; j < 2; j++){
            float4 i0 = *(const float4*)&ia[j*8];
            float4 i1 = *(const float4*)&ia[j*8+4];
            float4 l0 = *(const float4*)&la[j*8];
            float4 l1 = *(const float4*)&la[j*8+4];
            __nv_bfloat162 p0 = __floats2bfloat162_rn(tanh_hw(i0.x+l0.x), tanh_hw(i0.y+l0.y));
            __nv_bfloat162 p1 = __floats2bfloat162_rn(tanh_hw(i0.z+l0.z), tanh_hw(i0.w+l0.w));
            __nv_bfloat162 p2 = __floats2bfloat162_rn(tanh_hw(i1.x+l1.x), tanh_hw(i1.y+l1.y));
            __nv_bfloat162 p3 = __floats2bfloat162_rn(tanh_hw(i1.z+l1.z), tanh_hw(i1.w+l1.w));
            uint32_t rel = arel + j*16;
            uint32_t addr = sb + JSM_A0 + (rel ^ ((rel >> 3) & 0x70));
            asm volatile("st.shared.v4.b32 [%0], {%1,%2,%3,%4};"
                :: "r"(addr), "r"(*(uint32_t*)&p0), "r"(*(uint32_t*)&p1),
                   "r"(*(uint32_t*)&p2), "r"(*(uint32_t*)&p3));
        }
        cp_wait0();
    }
    __syncthreads();

    // -------- main loop --------
    for (int c = 0; c < 16; c++){
        const int s  = c & 1;
        const int hn = c*64 + 64;
        const uint32_t Ab = sb + (s ? JSM_A1 : JSM_A0);
        const uint32_t Bb = sb + (s ? JSM_B1 : JSM_B0);
        const uint32_t An = sb + (s ? JSM_A0 : JSM_A1);
        const uint32_t Bn = sb + (s ? JSM_B0 : JSM_B1);

        if (c < 15){
            const char* wsrc = (const char*)(g_w2bf + (size_t)rb*HH + hn + hbB);
            #pragma unroll
            for (int j = 0; j < 4; j++){
                uint32_t rel = brel + j*16;
                cp_async16(Bn + (rel ^ ((rel >> 3) & 0x70)), wsrc + j*16);
            }
            cp_commit();
        }

        // first half of A(c+1) prefetch
        float4 p0, p1;
        if (c < 15){
            const float* ia = imgp + (size_t)ra*HH + hn + qa;
            p0 = *(const float4*)&ia[0];
            p1 = *(const float4*)&ia[4];
        }

        #pragma unroll
        for (int half = 0; half < 2; half++){
            #pragma unroll
            for (int k2 = 0; k2 < 2; k2++){
                const int kk = half*2 + k2;
                const int colb = kk*32 + (lane >> 4)*16;
                uint32_t af[4];
                ldsm_x4(af, sw_addr(Ab, warp_m*16 + (lane & 15), colb));
                uint32_t bf[4][4];
                #pragma unroll
                for (int p = 0; p < 4; p++)
                    ldsm_x4(bf[p], sw_addr(Bb, warp_n*64 + p*16 + (lane & 15), colb));
                #pragma unroll
                for (int p = 0; p < 4; p++){
                    mma16816(acc[2*p  ], af, bf[p][0], bf[p][2]);
                    mma16816(acc[2*p+1], af, bf[p][1], bf[p][3]);
                }
            }
            // after each kstep pair: finish this half of A(c+1), start next half
            if (c < 15){
                const float* la = labp + hn + qa + half*8;
                float4 l0 = *(const float4*)&la[0];
                float4 l1 = *(const float4*)&la[4];
                __nv_bfloat162 q0 = __floats2bfloat162_rn(tanh_hw(p0.x+l0.x), tanh_hw(p0.y+l0.y));
                __nv_bfloat162 q1 = __floats2bfloat162_rn(tanh_hw(p0.z+l0.z), tanh_hw(p0.w+l0.w));
                __nv_bfloat162 q2 = __floats2bfloat162_rn(tanh_hw(p1.x+l1.x), tanh_hw(p1.y+l1.y));
                __nv_bfloat162 q3 = __floats2bfloat162_rn(tanh_hw(p1.z+l1.z), tanh_hw(p1.w+l1.w));
                uint32_t rel = arel + half*16;
                uint32_t addr = An + (rel ^ ((rel >> 3) & 0x70));
                asm volatile("st.shared.v4.b32 [%0], {%1,%2,%3,%4};"
                    :: "r"(addr), "r"(*(uint32_t*)&q0), "r"(*(uint32_t*)&q1),
                       "r"(*(uint32_t*)&q2), "r"(*(uint32_t*)&q3));
                if (half == 0){
                    const float* ia = imgp + (size_t)ra*HH + hn + qa + 8;
                    p0 = *(const float4*)&ia[0];
                    p1 = *(const float4*)&ia[4];
                }
            }
        }
        if (c < 15) cp_wait0();
        __syncthreads();
    }

    // ---- epilogue: +b2, log_softmax over k (row split across 2 n-warps) ----
    #pragma unroll
    for (int ni = 0; ni < 8; ni++){
        float2 bv = *(const float2*)&b2s[warp_n*64 + ni*8 + 2*lane4];
        acc[ni][0] += bv.x; acc[ni][1] += bv.y;
        acc[ni][2] += bv.x; acc[ni][3] += bv.y;
    }
    float rm[2];
    #pragma unroll
    for (int h = 0; h < 2; h++){
        float m = -1e30f;
        #pragma unroll
        for (int ni = 0; ni < 8; ni++)
            m = fmaxf(m, fmaxf(acc[ni][2*h], acc[ni][2*h+1]));
        #pragma unroll
        for (int d = 1; d < 4; d <<= 1)
            m = fmaxf(m, __shfl_xor_sync(0xffffffffu, m, d));
        rm[h] = m;
    }
    if (lane4 == 0){
        #pragma unroll
        for (int h = 0; h < 2; h++)
            redm[warp_n*64 + warp_m*16 + grp + 8*h] = rm[h];
    }
    __syncthreads();
    float mx[2], sm[2];
    #pragma unroll
    for (int h = 0; h < 2; h++){
        int row = warp_m*16 + grp + 8*h;
        mx[h] = fmaxf(redm[row], redm[64 + row]);
        float s = 0.f;
        #pragma unroll
        for (int ni = 0; ni < 8; ni++)
            s += __expf(acc[ni][2*h] - mx[h]) + __expf(acc[ni][2*h+1] - mx[h]);
        #pragma unroll
        for (int d = 1; d < 4; d <<= 1)
            s += __shfl_xor_sync(0xffffffffu, s, d);
        sm[h] = s;
    }
    if (lane4 == 0){
        #pragma unroll
        for (int h = 0; h < 2; h++)
            reds[warp_n*64 + warp_m*16 + grp + 8*h] = sm[h];
    }
    __syncthreads();
    float* outj = out + SEG_ELEMS + (size_t)(pair*TT + t0)*KK;
    #pragma unroll
    for (int h = 0; h < 2; h++){
        int row = warp_m*16 + grp + 8*h;
        float L = mx[h] + __logf(reds[row] + reds[64 + row]);
        float* orow = outj + row*KK + warp_n*64;
        #pragma unroll
        for (int ni = 0; ni < 8; ni++)
            *(float2*)&orow[ni*8 + 2*lane4] =
                make_float2(acc[ni][2*h] - L, acc[ni][2*h+1] - L);
    }
}

// ---------------------------------------------------------------------------
extern "C" void kernel_launch(void* const* d_in, const int* in_sizes, int n_in,
                              void* d_out, int out_size)
{
    (void)in_sizes; (void)n_in; (void)out_size;
    const float* img   = (const float*)d_in[0];  // (B,T,D)
    const float* lab   = (const float*)d_in[1];  // (B,U,D)
    const float* masks = (const float*)d_in[2];  // (B,1,T)
    const float* W1    = (const float*)d_in[3];  // (H,2D)
    const float* b1    = (const float*)d_in[4];  // (H)
    const float* W2    = (const float*)d_in[5];  // (K,H)
    const float* b2    = (const float*)d_in[6];  // (K)
    const float* convw = (const float*)d_in[7];  // (K,D)
    const float* convb = (const float*)d_in[8];  // (K)
    float* out = (float*)d_out;

    cudaFuncSetAttribute(prep_tc_kernel,
                         cudaFuncAttributeMaxDynamicSharedMemorySize, PSM_TOTAL);
    cudaFuncSetAttribute(joint_mma_kernel,
                         cudaFuncAttributeMaxDynamicSharedMemorySize, JSM_TOTAL);

    prep_tc_kernel<<<88, 256, PSM_TOTAL>>>(img, lab, W1, b1, convw, convb, masks, W2, out);
    joint_mma_kernel<<<768, 256, JSM_TOTAL>>>(b2, out);
}